// round 4
// baseline (speedup 1.0000x reference)
#include <cuda_runtime.h>
#include <cuda_bf16.h>
#include <math.h>
#include <stdint.h>

#define B_  8192
#define IN_ 1024
#define H_  2048
#define NH_ 4
#define HD_ 512
#define EPS_ 1e-5f

// ---------------------------------------------------------------------------
// Device scratch (allocation-free rule)
// ---------------------------------------------------------------------------
__device__ __align__(128) float g_buf0[(size_t)B_ * H_];   // x_proj (fp32)
__device__ __align__(128) float g_buf1[(size_t)B_ * H_];   // q -> gate (fp32)
__device__ __align__(128) float g_buf2[(size_t)B_ * H_];   // attn_gelu (fp32)

__device__ __align__(128) __nv_bfloat16 g_xs_hi[(size_t)B_ * IN_];
__device__ __align__(128) __nv_bfloat16 g_xs_lo[(size_t)B_ * IN_];
__device__ __align__(128) __nv_bfloat16 g_hs_hi[(size_t)B_ * H_];
__device__ __align__(128) __nv_bfloat16 g_hs_lo[(size_t)B_ * H_];
__device__ __align__(128) __nv_bfloat16 g_at_hi[(size_t)B_ * H_];
__device__ __align__(128) __nv_bfloat16 g_at_lo[(size_t)B_ * H_];
__device__ __align__(128) __nv_bfloat16 g_ag_hi[(size_t)B_ * H_];
__device__ __align__(128) __nv_bfloat16 g_ag_lo[(size_t)B_ * H_];

__device__ __align__(128) __nv_bfloat16 g_wp_hi[(size_t)H_ * IN_];
__device__ __align__(128) __nv_bfloat16 g_wp_lo[(size_t)H_ * IN_];
__device__ __align__(128) __nv_bfloat16 g_wq_hi[(size_t)H_ * H_];
__device__ __align__(128) __nv_bfloat16 g_wq_lo[(size_t)H_ * H_];
__device__ __align__(128) __nv_bfloat16 g_wo_hi[(size_t)H_ * H_];
__device__ __align__(128) __nv_bfloat16 g_wo_lo[(size_t)H_ * H_];
__device__ __align__(128) __nv_bfloat16 g_wg_hi[(size_t)H_ * 2 * H_];
__device__ __align__(128) __nv_bfloat16 g_wg_lo[(size_t)H_ * 2 * H_];

// ---------------------------------------------------------------------------
// PTX helpers (base-target-safe: cp.async / ldmatrix / mma.sync only)
// ---------------------------------------------------------------------------
__device__ __forceinline__ uint32_t smem_u32(const void* p) {
    uint32_t a;
    asm("{ .reg .u64 t; cvta.to.shared.u64 t, %1; cvt.u32.u64 %0, t; }" : "=r"(a) : "l"(p));
    return a;
}

#define CP_ASYNC16(sa, ga) \
    asm volatile("cp.async.cg.shared.global [%0], [%1], 16;\n" :: "r"(sa), "l"(ga))
#define CP_COMMIT()  asm volatile("cp.async.commit_group;\n" ::: "memory")
#define CP_WAIT0()   asm volatile("cp.async.wait_group 0;\n" ::: "memory")
#define CP_WAIT1()   asm volatile("cp.async.wait_group 1;\n" ::: "memory")

#define LDSM_X4(r0, r1, r2, r3, addr) \
    asm volatile("ldmatrix.sync.aligned.m8n8.x4.shared.b16 {%0,%1,%2,%3}, [%4];" \
        : "=r"(r0), "=r"(r1), "=r"(r2), "=r"(r3) : "r"(addr))

#define MMA_BF16(c0, c1, c2, c3, a0, a1, a2, a3, b0, b1) \
    asm volatile("mma.sync.aligned.m16n8k16.row.col.f32.bf16.bf16.f32 " \
        "{%0,%1,%2,%3}, {%4,%5,%6,%7}, {%8,%9}, {%0,%1,%2,%3};" \
        : "+f"(c0), "+f"(c1), "+f"(c2), "+f"(c3) \
        : "r"(a0), "r"(a1), "r"(a2), "r"(a3), "r"(b0), "r"(b1))

// ---------------------------------------------------------------------------
// SMEM geometry: per stage: Ah/Al 128x32, Bh/Bl 256x32 bf16, padded stride 40
// (80B rows -> conflict-free ldmatrix).
// ---------------------------------------------------------------------------
#define SSTR 40
#define A_ELEMS (128 * SSTR)               // 5120
#define BT_ELEMS (256 * SSTR)              // 10240
#define OFF_AH 0
#define OFF_AL A_ELEMS
#define OFF_BH (2 * A_ELEMS)
#define OFF_BL (2 * A_ELEMS + BT_ELEMS)
#define STAGE_ELEMS (2 * A_ELEMS + 2 * BT_ELEMS)   // 30720
#define SMEM_BYTES (2 * STAGE_ELEMS * 2)           // 122880

// ---------------------------------------------------------------------------
// Split-bf16 GEMM on HMMA:  C[M,N] = act( A @ B^T + bias )
// A logically = concat(A0[:, :Ks], A1[:, Ks:]) row-major (hi/lo pairs).
// CTA tile 128x256, warp tile 64x64, K-chunk 32, 2-stage cp.async pipeline.
// ACT: 0 none, 1 exact gelu, 2 sigmoid. SPLIT_OUT also writes bf16 hi/lo.
// ---------------------------------------------------------------------------
template<int ACT, bool SPLIT_OUT>
__global__ void __launch_bounds__(256, 1)
gemm_mma(const __nv_bfloat16* __restrict__ a0h, const __nv_bfloat16* __restrict__ a0l,
         const __nv_bfloat16* __restrict__ a1h, const __nv_bfloat16* __restrict__ a1l, int Ks,
         const __nv_bfloat16* __restrict__ bhp, const __nv_bfloat16* __restrict__ blp,
         const float* __restrict__ bias, float* __restrict__ C,
         __nv_bfloat16* __restrict__ ohi, __nv_bfloat16* __restrict__ olo,
         int M, int N, int K)
{
    extern __shared__ __align__(128) char smem[];
    const uint32_t sbase = smem_u32(smem);
    const int tid  = threadIdx.x;
    const int warp = tid >> 5;
    const int lane = tid & 31;
    const int bm = blockIdx.y * 128;
    const int bn = blockIdx.x * 256;
    const int wm = (warp >> 2) * 64;       // 0 or 64
    const int wn = (warp & 3) * 64;        // 0..192

    float acc[4][8][4];
#pragma unroll
    for (int i = 0; i < 4; i++)
#pragma unroll
        for (int j = 0; j < 8; j++)
#pragma unroll
            for (int r = 0; r < 4; r++) acc[i][j][r] = 0.0f;

    const int nk = K / 32;

    // ---- stage loader ----
    auto load_stage = [&](int stage, int k0) {
        const __nv_bfloat16 *ah, *al;
        int lda, kk;
        if (k0 < Ks) { ah = a0h; al = a0l; lda = Ks;     kk = k0; }
        else         { ah = a1h; al = a1l; lda = K - Ks; kk = k0 - Ks; }
        const uint32_t stb = sbase + (uint32_t)stage * STAGE_ELEMS * 2;
#pragma unroll
        for (int r = 0; r < 2; r++) {                   // A: 512 chunks
            const int c   = tid + r * 256;
            const int row = c >> 2;
            const int seg = c & 3;
            const uint32_t so = stb + (uint32_t)(row * SSTR + seg * 8) * 2;
            const size_t ga = (size_t)(bm + row) * lda + kk + seg * 8;
            CP_ASYNC16(so + OFF_AH * 2, ah + ga);
            CP_ASYNC16(so + OFF_AL * 2, al + ga);
        }
#pragma unroll
        for (int r = 0; r < 4; r++) {                   // B: 1024 chunks
            const int c   = tid + r * 256;
            const int row = c >> 2;
            const int seg = c & 3;
            const uint32_t so = stb + (uint32_t)(row * SSTR + seg * 8) * 2;
            const size_t gb = (size_t)(bn + row) * K + k0 + seg * 8;
            CP_ASYNC16(so + OFF_BH * 2, bhp + gb);
            CP_ASYNC16(so + OFF_BL * 2, blp + gb);
        }
        CP_COMMIT();
    };

    // ldmatrix lane geometry
    const int lrow = (lane & 7) + ((lane >> 3) & 1) * 8;   // 0..15
    const int lcol = (lane >> 4) * 8;                      // 0 or 8

    load_stage(0, 0);

    for (int kc = 0; kc < nk; kc++) {
        if (kc + 1 < nk) { load_stage((kc + 1) & 1, (kc + 1) * 32); CP_WAIT1(); }
        else             { CP_WAIT0(); }
        __syncthreads();

        const uint32_t stb = sbase + (uint32_t)(kc & 1) * STAGE_ELEMS * 2;
#pragma unroll
        for (int ks = 0; ks < 2; ks++) {
            const int kb = ks * 16 + lcol;
            uint32_t ah[4][4], al[4][4];
#pragma unroll
            for (int i = 0; i < 4; i++) {
                const uint32_t ad = stb + (uint32_t)((wm + i * 16 + lrow) * SSTR + kb) * 2;
                LDSM_X4(ah[i][0], ah[i][1], ah[i][2], ah[i][3], ad + OFF_AH * 2);
                LDSM_X4(al[i][0], al[i][1], al[i][2], al[i][3], ad + OFF_AL * 2);
            }
#pragma unroll
            for (int p = 0; p < 4; p++) {
                const uint32_t bd = stb + (uint32_t)((wn + p * 16 + lrow) * SSTR + kb) * 2;
                uint32_t h0, h1, h2, h3, l0, l1, l2, l3;
                LDSM_X4(h0, h1, h2, h3, bd + OFF_BH * 2);
                LDSM_X4(l0, l1, l2, l3, bd + OFF_BL * 2);
                const int j0 = 2 * p, j1 = 2 * p + 1;
#pragma unroll
                for (int i = 0; i < 4; i++) {
                    float* c0 = acc[i][j0];
                    float* c1 = acc[i][j1];
                    MMA_BF16(c0[0], c0[1], c0[2], c0[3],
                             ah[i][0], ah[i][1], ah[i][2], ah[i][3], h0, h2);
                    MMA_BF16(c1[0], c1[1], c1[2], c1[3],
                             ah[i][0], ah[i][1], ah[i][2], ah[i][3], h1, h3);
                    MMA_BF16(c0[0], c0[1], c0[2], c0[3],
                             ah[i][0], ah[i][1], ah[i][2], ah[i][3], l0, l2);
                    MMA_BF16(c1[0], c1[1], c1[2], c1[3],
                             ah[i][0], ah[i][1], ah[i][2], ah[i][3], l1, l3);
                    MMA_BF16(c0[0], c0[1], c0[2], c0[3],
                             al[i][0], al[i][1], al[i][2], al[i][3], h0, h2);
                    MMA_BF16(c1[0], c1[1], c1[2], c1[3],
                             al[i][0], al[i][1], al[i][2], al[i][3], h1, h3);
                }
            }
        }
        __syncthreads();
    }

    // ---- epilogue: bias + activation (+ optional bf16 split) ----
    const int tr = lane >> 2;
    const int tc = (lane & 3) * 2;
#pragma unroll
    for (int i = 0; i < 4; i++) {
        const int r0 = bm + wm + i * 16 + tr;
        const int r1 = r0 + 8;
#pragma unroll
        for (int j = 0; j < 8; j++) {
            const int col = bn + wn + j * 8 + tc;
            const float b0 = bias[col], b1 = bias[col + 1];
            float v[4] = {acc[i][j][0] + b0, acc[i][j][1] + b1,
                          acc[i][j][2] + b0, acc[i][j][3] + b1};
#pragma unroll
            for (int r = 0; r < 4; r++) {
                if (ACT == 1)      v[r] = 0.5f * v[r] * (1.0f + erff(v[r] * 0.70710678118654752f));
                else if (ACT == 2) v[r] = 1.0f / (1.0f + expf(-v[r]));
            }
            *(float2*)(C + (size_t)r0 * N + col) = make_float2(v[0], v[1]);
            *(float2*)(C + (size_t)r1 * N + col) = make_float2(v[2], v[3]);
            if (SPLIT_OUT) {
                __nv_bfloat16 h0 = __float2bfloat16(v[0]), h1 = __float2bfloat16(v[1]);
                __nv_bfloat16 h2 = __float2bfloat16(v[2]), h3 = __float2bfloat16(v[3]);
                __nv_bfloat16 q0 = __float2bfloat16(v[0] - __bfloat162float(h0));
                __nv_bfloat16 q1 = __float2bfloat16(v[1] - __bfloat162float(h1));
                __nv_bfloat16 q2 = __float2bfloat16(v[2] - __bfloat162float(h2));
                __nv_bfloat16 q3 = __float2bfloat16(v[3] - __bfloat162float(h3));
                *(__nv_bfloat162*)(ohi + (size_t)r0 * N + col) = __nv_bfloat162{h0, h1};
                *(__nv_bfloat162*)(ohi + (size_t)r1 * N + col) = __nv_bfloat162{h2, h3};
                *(__nv_bfloat162*)(olo + (size_t)r0 * N + col) = __nv_bfloat162{q0, q1};
                *(__nv_bfloat162*)(olo + (size_t)r1 * N + col) = __nv_bfloat162{q2, q3};
            }
        }
    }
}

// ---------------------------------------------------------------------------
// fp32 -> (bf16 hi, bf16 lo) split
// ---------------------------------------------------------------------------
__global__ void __launch_bounds__(256)
split_kernel(const float* __restrict__ in, __nv_bfloat16* __restrict__ hi,
             __nv_bfloat16* __restrict__ lo, int n4)
{
    int i = blockIdx.x * 256 + threadIdx.x;
    if (i >= n4) return;
    float4 v = ((const float4*)in)[i];
    __nv_bfloat16 h0 = __float2bfloat16(v.x), h1 = __float2bfloat16(v.y);
    __nv_bfloat16 h2 = __float2bfloat16(v.z), h3 = __float2bfloat16(v.w);
    __nv_bfloat16 l0 = __float2bfloat16(v.x - __bfloat162float(h0));
    __nv_bfloat16 l1 = __float2bfloat16(v.y - __bfloat162float(h1));
    __nv_bfloat16 l2 = __float2bfloat16(v.z - __bfloat162float(h2));
    __nv_bfloat16 l3 = __float2bfloat16(v.w - __bfloat162float(h3));
    ((__nv_bfloat162*)hi)[2*i]   = __nv_bfloat162{h0, h1};
    ((__nv_bfloat162*)hi)[2*i+1] = __nv_bfloat162{h2, h3};
    ((__nv_bfloat162*)lo)[2*i]   = __nv_bfloat162{l0, l1};
    ((__nv_bfloat162*)lo)[2*i+1] = __nv_bfloat162{l2, l3};
}

// ---------------------------------------------------------------------------
// 4-key attention; writes attn directly as bf16 hi/lo split.
// ---------------------------------------------------------------------------
__global__ void __launch_bounds__(256)
attn_kernel(const float* __restrict__ h_prev, const float* __restrict__ xproj,
            const float* __restrict__ q,
            __nv_bfloat16* __restrict__ ahi, __nv_bfloat16* __restrict__ alo)
{
    const int gw   = (blockIdx.x * 256 + threadIdx.x) >> 5;
    const int lane = threadIdx.x & 31;
    if (gw >= B_ * NH_) return;
    const size_t base = (size_t)(gw / NH_) * H_ + (size_t)(gw % NH_) * HD_;

    const float4* qp = (const float4*)(q + base);
    const float4* hp = (const float4*)(h_prev + base);
    const float4* xp = (const float4*)(xproj + base);

    float s0 = 0.f, s1 = 0.f, s3 = 0.f;
    float4 hv[4], xv[4];
#pragma unroll
    for (int i = 0; i < 4; i++) {
        float4 q4 = qp[i * 32 + lane];
        float4 h4 = hp[i * 32 + lane];
        float4 x4 = xp[i * 32 + lane];
        hv[i] = h4; xv[i] = x4;
        s0 += q4.x * h4.x + q4.y * h4.y + q4.z * h4.z + q4.w * h4.w;
        s1 += q4.x * x4.x + q4.y * x4.y + q4.z * x4.z + q4.w * x4.w;
        s3 += q4.x * h4.x * x4.x + q4.y * h4.y * x4.y +
              q4.z * h4.z * x4.z + q4.w * h4.w * x4.w;
    }
#pragma unroll
    for (int off = 16; off > 0; off >>= 1) {
        s0 += __shfl_xor_sync(0xffffffffu, s0, off);
        s1 += __shfl_xor_sync(0xffffffffu, s1, off);
        s3 += __shfl_xor_sync(0xffffffffu, s3, off);
    }
    const float inv = rsqrtf((float)HD_);
    float sc0 = s0 * inv, sc1 = s1 * inv, sc2 = (s0 + s1) * inv, sc3 = s3 * inv;
    float m  = fmaxf(fmaxf(sc0, sc1), fmaxf(sc2, sc3));
    float e0 = expf(sc0 - m), e1 = expf(sc1 - m), e2 = expf(sc2 - m), e3 = expf(sc3 - m);
    float rs = 1.0f / (e0 + e1 + e2 + e3);
    float w0 = e0 * rs, w1 = e1 * rs, w2 = e2 * rs, w3 = e3 * rs;
    float ch = w0 + w2, cx = w1 + w2;

    __nv_bfloat162* ohp = (__nv_bfloat162*)(ahi + base);
    __nv_bfloat162* olp = (__nv_bfloat162*)(alo + base);
#pragma unroll
    for (int i = 0; i < 4; i++) {
        float4 h4 = hv[i], x4 = xv[i];
        float o0 = ch * h4.x + cx * x4.x + w3 * h4.x * x4.x;
        float o1 = ch * h4.y + cx * x4.y + w3 * h4.y * x4.y;
        float o2 = ch * h4.z + cx * x4.z + w3 * h4.z * x4.z;
        float o3 = ch * h4.w + cx * x4.w + w3 * h4.w * x4.w;
        __nv_bfloat16 h0 = __float2bfloat16(o0), h1 = __float2bfloat16(o1);
        __nv_bfloat16 h2 = __float2bfloat16(o2), h3 = __float2bfloat16(o3);
        __nv_bfloat16 l0 = __float2bfloat16(o0 - __bfloat162float(h0));
        __nv_bfloat16 l1 = __float2bfloat16(o1 - __bfloat162float(h1));
        __nv_bfloat16 l2 = __float2bfloat16(o2 - __bfloat162float(h2));
        __nv_bfloat16 l3 = __float2bfloat16(o3 - __bfloat162float(h3));
        int idx = (i * 32 + lane) * 2;
        ohp[idx]   = __nv_bfloat162{h0, h1};
        ohp[idx+1] = __nv_bfloat162{h2, h3};
        olp[idx]   = __nv_bfloat162{l0, l1};
        olp[idx+1] = __nv_bfloat162{l2, l3};
    }
}

// ---------------------------------------------------------------------------
// LayerNorm + gated mix
// ---------------------------------------------------------------------------
__global__ void __launch_bounds__(256)
ln_gate_kernel(const float* __restrict__ attn_g, const float* __restrict__ h_prev,
               const float* __restrict__ gate, const float* __restrict__ gamma,
               const float* __restrict__ beta, float* __restrict__ out)
{
    const int b   = blockIdx.x;
    const int tid = threadIdx.x;
    const size_t rb = (size_t)b * H_;

    float4 y[2], h4[2];
    float sum = 0.f, sq = 0.f;
#pragma unroll
    for (int c = 0; c < 2; c++) {
        int d = c * 1024 + tid * 4;
        float4 a  = *(const float4*)(attn_g + rb + d);
        float4 hh = *(const float4*)(h_prev + rb + d);
        float4 yy = make_float4(a.x + hh.x, a.y + hh.y, a.z + hh.z, a.w + hh.w);
        y[c] = yy; h4[c] = hh;
        sum += yy.x + yy.y + yy.z + yy.w;
        sq  += yy.x * yy.x + yy.y * yy.y + yy.z * yy.z + yy.w * yy.w;
    }
#pragma unroll
    for (int off = 16; off > 0; off >>= 1) {
        sum += __shfl_xor_sync(0xffffffffu, sum, off);
        sq  += __shfl_xor_sync(0xffffffffu, sq,  off);
    }
    __shared__ float s_sum[8], s_sq[8];
    __shared__ float s_mu, s_rstd;
    if ((tid & 31) == 0) { s_sum[tid >> 5] = sum; s_sq[tid >> 5] = sq; }
    __syncthreads();
    if (tid == 0) {
        float S = 0.f, Q = 0.f;
#pragma unroll
        for (int i = 0; i < 8; i++) { S += s_sum[i]; Q += s_sq[i]; }
        float mu  = S / (float)H_;
        float var = Q / (float)H_ - mu * mu;
        s_mu = mu;
        s_rstd = rsqrtf(var + EPS_);
    }
    __syncthreads();
    const float mu = s_mu, rstd = s_rstd;

#pragma unroll
    for (int c = 0; c < 2; c++) {
        int d = c * 1024 + tid * 4;
        float4 g4 = *(const float4*)(gate  + rb + d);
        float4 gm = *(const float4*)(gamma + d);
        float4 bt = *(const float4*)(beta  + d);
        float4 yy = y[c], hh = h4[c], o;
        float c0 = (yy.x - mu) * rstd * gm.x + bt.x;
        float c1 = (yy.y - mu) * rstd * gm.y + bt.y;
        float c2 = (yy.z - mu) * rstd * gm.z + bt.z;
        float c3 = (yy.w - mu) * rstd * gm.w + bt.w;
        o.x = g4.x * c0 + (1.0f - g4.x) * hh.x;
        o.y = g4.y * c1 + (1.0f - g4.y) * hh.y;
        o.z = g4.z * c2 + (1.0f - g4.z) * hh.z;
        o.w = g4.w * c3 + (1.0f - g4.w) * hh.w;
        *(float4*)(out + rb + d) = o;
    }
}

// ---------------------------------------------------------------------------
extern "C" void kernel_launch(void* const* d_in, const int* in_sizes, int n_in,
                              void* d_out, int out_size)
{
    const float* h_prev = (const float*)d_in[0];
    const float* x      = (const float*)d_in[1];
    const float* W_proj = (const float*)d_in[2];
    const float* b_proj = (const float*)d_in[3];
    const float* W_q    = (const float*)d_in[4];
    const float* b_q    = (const float*)d_in[5];
    const float* W_o    = (const float*)d_in[6];
    const float* b_o    = (const float*)d_in[7];
    const float* W_g    = (const float*)d_in[8];
    const float* b_g    = (const float*)d_in[9];
    const float* gamma  = (const float*)d_in[10];
    const float* beta   = (const float*)d_in[11];
    float* out = (float*)d_out;

    float *buf0, *buf1, *buf2;
    __nv_bfloat16 *xsh, *xsl, *hsh, *hsl, *ath, *atl, *agh, *agl;
    __nv_bfloat16 *wph, *wpl, *wqh, *wql, *woh, *wol, *wgh, *wgl;
    cudaGetSymbolAddress((void**)&buf0, g_buf0);
    cudaGetSymbolAddress((void**)&buf1, g_buf1);
    cudaGetSymbolAddress((void**)&buf2, g_buf2);
    cudaGetSymbolAddress((void**)&xsh, g_xs_hi);
    cudaGetSymbolAddress((void**)&xsl, g_xs_lo);
    cudaGetSymbolAddress((void**)&hsh, g_hs_hi);
    cudaGetSymbolAddress((void**)&hsl, g_hs_lo);
    cudaGetSymbolAddress((void**)&ath, g_at_hi);
    cudaGetSymbolAddress((void**)&atl, g_at_lo);
    cudaGetSymbolAddress((void**)&agh, g_ag_hi);
    cudaGetSymbolAddress((void**)&agl, g_ag_lo);
    cudaGetSymbolAddress((void**)&wph, g_wp_hi);
    cudaGetSymbolAddress((void**)&wpl, g_wp_lo);
    cudaGetSymbolAddress((void**)&wqh, g_wq_hi);
    cudaGetSymbolAddress((void**)&wql, g_wq_lo);
    cudaGetSymbolAddress((void**)&woh, g_wo_hi);
    cudaGetSymbolAddress((void**)&wol, g_wo_lo);
    cudaGetSymbolAddress((void**)&wgh, g_wg_hi);
    cudaGetSymbolAddress((void**)&wgl, g_wg_lo);

    cudaFuncSetAttribute(gemm_mma<0, false>, cudaFuncAttributeMaxDynamicSharedMemorySize, SMEM_BYTES);
    cudaFuncSetAttribute(gemm_mma<1, true >, cudaFuncAttributeMaxDynamicSharedMemorySize, SMEM_BYTES);
    cudaFuncSetAttribute(gemm_mma<2, false>, cudaFuncAttributeMaxDynamicSharedMemorySize, SMEM_BYTES);

    // splits of inputs/weights
    {
        int n4;
        n4 = B_ * IN_ / 4;     split_kernel<<<n4 / 256, 256>>>(x, xsh, xsl, n4);
        n4 = B_ * H_ / 4;      split_kernel<<<n4 / 256, 256>>>(h_prev, hsh, hsl, n4);
        n4 = H_ * IN_ / 4;     split_kernel<<<n4 / 256, 256>>>(W_proj, wph, wpl, n4);
        n4 = H_ * H_ / 4;      split_kernel<<<n4 / 256, 256>>>(W_q, wqh, wql, n4);
        n4 = H_ * H_ / 4;      split_kernel<<<n4 / 256, 256>>>(W_o, woh, wol, n4);
        n4 = H_ * 2 * H_ / 4;  split_kernel<<<n4 / 256, 256>>>(W_g, wgh, wgl, n4);
    }

    dim3 grid(H_ / 256, B_ / 128);   // (8, 64)

    // 1) x_proj = x @ W_proj^T + b_proj            -> buf0
    gemm_mma<0, false><<<grid, 256, SMEM_BYTES>>>(
        xsh, xsl, xsh, xsl, IN_, wph, wpl, b_proj, buf0, nullptr, nullptr,
        B_, H_, IN_);
    // 2) q = h_prev @ W_q^T + b_q                  -> buf1
    gemm_mma<0, false><<<grid, 256, SMEM_BYTES>>>(
        hsh, hsl, hsh, hsl, H_, wqh, wql, b_q, buf1, nullptr, nullptr,
        B_, H_, H_);
    // 3) attention -> attn split (bf16 hi/lo)
    attn_kernel<<<(B_ * NH_) / 8, 256>>>(h_prev, buf0, buf1, ath, atl);
    // 4) attn_gelu = gelu(attn @ W_o^T + b_o)      -> buf2 (fp32) + bf16 split
    gemm_mma<1, true><<<grid, 256, SMEM_BYTES>>>(
        ath, atl, ath, atl, H_, woh, wol, b_o, buf2, agh, agl,
        B_, H_, H_);
    // 5) gate = sigmoid([h_prev, attn_gelu] @ W_g^T + b_g) -> buf1
    gemm_mma<2, false><<<grid, 256, SMEM_BYTES>>>(
        hsh, hsl, agh, agl, H_, wgh, wgl, b_g, buf1, nullptr, nullptr,
        B_, H_, 2 * H_);
    // 6) layernorm + gated mix                     -> out
    ln_gate_kernel<<<B_, 256>>>(buf2, h_prev, buf1, gamma, beta, out);
}

// round 5
// speedup vs baseline: 1.4010x; 1.4010x over previous
#include <cuda_runtime.h>
#include <cuda_fp16.h>
#include <math.h>
#include <stdint.h>

#define B_  8192
#define IN_ 1024
#define H_  2048
#define NH_ 4
#define HD_ 512
#define EPS_ 1e-5f

// ---------------------------------------------------------------------------
// Device scratch (allocation-free rule)
// ---------------------------------------------------------------------------
__device__ __align__(128) float g_buf0[(size_t)B_ * H_];   // x_proj (fp32)
__device__ __align__(128) float g_buf1[(size_t)B_ * H_];   // q -> gate (fp32)
__device__ __align__(128) float g_buf2[(size_t)B_ * H_];   // attn_gelu (fp32)

// activations: fp16 hi only
__device__ __align__(128) __half g_xs_h[(size_t)B_ * IN_];
__device__ __align__(128) __half g_hs_h[(size_t)B_ * H_];
__device__ __align__(128) __half g_at_h[(size_t)B_ * H_];
__device__ __align__(128) __half g_ag_h[(size_t)B_ * H_];

// weights: fp16 hi + lo
__device__ __align__(128) __half g_wp_hi[(size_t)H_ * IN_];
__device__ __align__(128) __half g_wp_lo[(size_t)H_ * IN_];
__device__ __align__(128) __half g_wq_hi[(size_t)H_ * H_];
__device__ __align__(128) __half g_wq_lo[(size_t)H_ * H_];
__device__ __align__(128) __half g_wo_hi[(size_t)H_ * H_];
__device__ __align__(128) __half g_wo_lo[(size_t)H_ * H_];
__device__ __align__(128) __half g_wg_hi[(size_t)H_ * 2 * H_];
__device__ __align__(128) __half g_wg_lo[(size_t)H_ * 2 * H_];

// ---------------------------------------------------------------------------
// PTX helpers (base-target-safe)
// ---------------------------------------------------------------------------
__device__ __forceinline__ uint32_t smem_u32(const void* p) {
    uint32_t a;
    asm("{ .reg .u64 t; cvta.to.shared.u64 t, %1; cvt.u32.u64 %0, t; }" : "=r"(a) : "l"(p));
    return a;
}

#define CP_ASYNC16(sa, ga) \
    asm volatile("cp.async.cg.shared.global [%0], [%1], 16;\n" :: "r"(sa), "l"(ga))
#define CP_COMMIT()  asm volatile("cp.async.commit_group;\n" ::: "memory")
#define CP_WAIT0()   asm volatile("cp.async.wait_group 0;\n" ::: "memory")
#define CP_WAIT1()   asm volatile("cp.async.wait_group 1;\n" ::: "memory")

#define LDSM_X4(r0, r1, r2, r3, addr) \
    asm volatile("ldmatrix.sync.aligned.m8n8.x4.shared.b16 {%0,%1,%2,%3}, [%4];" \
        : "=r"(r0), "=r"(r1), "=r"(r2), "=r"(r3) : "r"(addr))

#define MMA_F16(c0, c1, c2, c3, a0, a1, a2, a3, b0, b1) \
    asm volatile("mma.sync.aligned.m16n8k16.row.col.f32.f16.f16.f32 " \
        "{%0,%1,%2,%3}, {%4,%5,%6,%7}, {%8,%9}, {%0,%1,%2,%3};" \
        : "+f"(c0), "+f"(c1), "+f"(c2), "+f"(c3) \
        : "r"(a0), "r"(a1), "r"(a2), "r"(a3), "r"(b0), "r"(b1))

// ---------------------------------------------------------------------------
// SMEM: per stage: A 128x32 fp16 (hi only), Bh/Bl 256x32 fp16.
// Padded stride 40 elems (80B rows -> conflict-free ldmatrix).
// ---------------------------------------------------------------------------
#define SSTR 40
#define A_ELEMS (128 * SSTR)               // 5120
#define BT_ELEMS (256 * SSTR)              // 10240
#define OFF_AH 0
#define OFF_BH A_ELEMS
#define OFF_BL (A_ELEMS + BT_ELEMS)
#define STAGE_ELEMS (A_ELEMS + 2 * BT_ELEMS)       // 25600
#define SMEM_BYTES (2 * STAGE_ELEMS * 2)           // 102400

// ---------------------------------------------------------------------------
// 2-term fp16-split GEMM on HMMA:  C[M,N] = act( A @ B^T + bias )
// acc = Ah*Bh + Ah*Bl ; error = (A - Ah)*B ~ 2^-12 relative.
// A logically = concat(A0[:, :Ks], A1[:, Ks:]) row-major, fp16.
// CTA tile 128x256, warp tile 64x64, K-chunk 32, 2-stage cp.async pipeline.
// ACT: 0 none, 1 exact gelu, 2 sigmoid. SPLIT_OUT also writes fp16 hi.
// ---------------------------------------------------------------------------
template<int ACT, bool SPLIT_OUT>
__global__ void __launch_bounds__(256, 1)
gemm_mma(const __half* __restrict__ a0h, const __half* __restrict__ a1h, int Ks,
         const __half* __restrict__ bhp, const __half* __restrict__ blp,
         const float* __restrict__ bias, float* __restrict__ C,
         __half* __restrict__ ohi,
         int M, int N, int K)
{
    extern __shared__ __align__(128) char smem[];
    const uint32_t sbase = smem_u32(smem);
    const int tid  = threadIdx.x;
    const int warp = tid >> 5;
    const int lane = tid & 31;
    const int bm = blockIdx.y * 128;
    const int bn = blockIdx.x * 256;
    const int wm = (warp >> 2) * 64;       // 0 or 64
    const int wn = (warp & 3) * 64;        // 0..192

    float acc[4][8][4];
#pragma unroll
    for (int i = 0; i < 4; i++)
#pragma unroll
        for (int j = 0; j < 8; j++)
#pragma unroll
            for (int r = 0; r < 4; r++) acc[i][j][r] = 0.0f;

    const int nk = K / 32;

    // ---- stage loader ----
    auto load_stage = [&](int stage, int k0) {
        const __half* ah;
        int lda, kk;
        if (k0 < Ks) { ah = a0h; lda = Ks;     kk = k0; }
        else         { ah = a1h; lda = K - Ks; kk = k0 - Ks; }
        const uint32_t stb = sbase + (uint32_t)stage * STAGE_ELEMS * 2;
#pragma unroll
        for (int r = 0; r < 2; r++) {                   // A: 512 chunks
            const int c   = tid + r * 256;
            const int row = c >> 2;
            const int seg = c & 3;
            const uint32_t so = stb + (uint32_t)(row * SSTR + seg * 8) * 2;
            const size_t ga = (size_t)(bm + row) * lda + kk + seg * 8;
            CP_ASYNC16(so + OFF_AH * 2, ah + ga);
        }
#pragma unroll
        for (int r = 0; r < 4; r++) {                   // B: 1024 chunks
            const int c   = tid + r * 256;
            const int row = c >> 2;
            const int seg = c & 3;
            const uint32_t so = stb + (uint32_t)(row * SSTR + seg * 8) * 2;
            const size_t gb = (size_t)(bn + row) * K + k0 + seg * 8;
            CP_ASYNC16(so + OFF_BH * 2, bhp + gb);
            CP_ASYNC16(so + OFF_BL * 2, blp + gb);
        }
        CP_COMMIT();
    };

    // ldmatrix lane geometry
    const int lrow = (lane & 7) + ((lane >> 3) & 1) * 8;   // 0..15
    const int lcol = (lane >> 4) * 8;                      // 0 or 8

    load_stage(0, 0);

    for (int kc = 0; kc < nk; kc++) {
        if (kc + 1 < nk) { load_stage((kc + 1) & 1, (kc + 1) * 32); CP_WAIT1(); }
        else             { CP_WAIT0(); }
        __syncthreads();

        const uint32_t stb = sbase + (uint32_t)(kc & 1) * STAGE_ELEMS * 2;
#pragma unroll
        for (int ks = 0; ks < 2; ks++) {
            const int kb = ks * 16 + lcol;
            uint32_t ah[4][4];
#pragma unroll
            for (int i = 0; i < 4; i++) {
                const uint32_t ad = stb + (uint32_t)((wm + i * 16 + lrow) * SSTR + kb) * 2;
                LDSM_X4(ah[i][0], ah[i][1], ah[i][2], ah[i][3], ad + OFF_AH * 2);
            }
#pragma unroll
            for (int p = 0; p < 4; p++) {
                const uint32_t bd = stb + (uint32_t)((wn + p * 16 + lrow) * SSTR + kb) * 2;
                uint32_t h0, h1, h2, h3, l0, l1, l2, l3;
                LDSM_X4(h0, h1, h2, h3, bd + OFF_BH * 2);
                LDSM_X4(l0, l1, l2, l3, bd + OFF_BL * 2);
                const int j0 = 2 * p, j1 = 2 * p + 1;
#pragma unroll
                for (int i = 0; i < 4; i++) {
                    float* c0 = acc[i][j0];
                    float* c1 = acc[i][j1];
                    MMA_F16(c0[0], c0[1], c0[2], c0[3],
                            ah[i][0], ah[i][1], ah[i][2], ah[i][3], h0, h2);
                    MMA_F16(c1[0], c1[1], c1[2], c1[3],
                            ah[i][0], ah[i][1], ah[i][2], ah[i][3], h1, h3);
                    MMA_F16(c0[0], c0[1], c0[2], c0[3],
                            ah[i][0], ah[i][1], ah[i][2], ah[i][3], l0, l2);
                    MMA_F16(c1[0], c1[1], c1[2], c1[3],
                            ah[i][0], ah[i][1], ah[i][2], ah[i][3], l1, l3);
                }
            }
        }
        __syncthreads();
    }

    // ---- epilogue: bias + activation (+ optional fp16 hi out) ----
    const int tr = lane >> 2;
    const int tc = (lane & 3) * 2;
#pragma unroll
    for (int i = 0; i < 4; i++) {
        const int r0 = bm + wm + i * 16 + tr;
        const int r1 = r0 + 8;
#pragma unroll
        for (int j = 0; j < 8; j++) {
            const int col = bn + wn + j * 8 + tc;
            const float b0 = bias[col], b1 = bias[col + 1];
            float v[4] = {acc[i][j][0] + b0, acc[i][j][1] + b1,
                          acc[i][j][2] + b0, acc[i][j][3] + b1};
#pragma unroll
            for (int r = 0; r < 4; r++) {
                if (ACT == 1)      v[r] = 0.5f * v[r] * (1.0f + erff(v[r] * 0.70710678118654752f));
                else if (ACT == 2) v[r] = 1.0f / (1.0f + expf(-v[r]));
            }
            *(float2*)(C + (size_t)r0 * N + col) = make_float2(v[0], v[1]);
            *(float2*)(C + (size_t)r1 * N + col) = make_float2(v[2], v[3]);
            if (SPLIT_OUT) {
                *(__half2*)(ohi + (size_t)r0 * N + col) =
                    __floats2half2_rn(v[0], v[1]);
                *(__half2*)(ohi + (size_t)r1 * N + col) =
                    __floats2half2_rn(v[2], v[3]);
            }
        }
    }
}

// ---------------------------------------------------------------------------
// fp32 -> fp16 (activations)
// ---------------------------------------------------------------------------
__global__ void __launch_bounds__(256)
split_a_kernel(const float* __restrict__ in, __half* __restrict__ hi, int n4)
{
    int i = blockIdx.x * 256 + threadIdx.x;
    if (i >= n4) return;
    float4 v = ((const float4*)in)[i];
    ((__half2*)hi)[2*i]   = __floats2half2_rn(v.x, v.y);
    ((__half2*)hi)[2*i+1] = __floats2half2_rn(v.z, v.w);
}

// ---------------------------------------------------------------------------
// fp32 -> (fp16 hi, fp16 lo) split (weights)
// ---------------------------------------------------------------------------
__global__ void __launch_bounds__(256)
split_w_kernel(const float* __restrict__ in, __half* __restrict__ hi,
               __half* __restrict__ lo, int n4)
{
    int i = blockIdx.x * 256 + threadIdx.x;
    if (i >= n4) return;
    float4 v = ((const float4*)in)[i];
    __half h0 = __float2half_rn(v.x), h1 = __float2half_rn(v.y);
    __half h2 = __float2half_rn(v.z), h3 = __float2half_rn(v.w);
    __half l0 = __float2half_rn(v.x - __half2float(h0));
    __half l1 = __float2half_rn(v.y - __half2float(h1));
    __half l2 = __float2half_rn(v.z - __half2float(h2));
    __half l3 = __float2half_rn(v.w - __half2float(h3));
    ((__half2*)hi)[2*i]   = __half2{h0, h1};
    ((__half2*)hi)[2*i+1] = __half2{h2, h3};
    ((__half2*)lo)[2*i]   = __half2{l0, l1};
    ((__half2*)lo)[2*i+1] = __half2{l2, l3};
}

// ---------------------------------------------------------------------------
// 4-key attention; writes attn as fp16.
// ---------------------------------------------------------------------------
__global__ void __launch_bounds__(256)
attn_kernel(const float* __restrict__ h_prev, const float* __restrict__ xproj,
            const float* __restrict__ q, __half* __restrict__ ah)
{
    const int gw   = (blockIdx.x * 256 + threadIdx.x) >> 5;
    const int lane = threadIdx.x & 31;
    if (gw >= B_ * NH_) return;
    const size_t base = (size_t)(gw / NH_) * H_ + (size_t)(gw % NH_) * HD_;

    const float4* qp = (const float4*)(q + base);
    const float4* hp = (const float4*)(h_prev + base);
    const float4* xp = (const float4*)(xproj + base);

    float s0 = 0.f, s1 = 0.f, s3 = 0.f;
    float4 hv[4], xv[4];
#pragma unroll
    for (int i = 0; i < 4; i++) {
        float4 q4 = qp[i * 32 + lane];
        float4 h4 = hp[i * 32 + lane];
        float4 x4 = xp[i * 32 + lane];
        hv[i] = h4; xv[i] = x4;
        s0 += q4.x * h4.x + q4.y * h4.y + q4.z * h4.z + q4.w * h4.w;
        s1 += q4.x * x4.x + q4.y * x4.y + q4.z * x4.z + q4.w * x4.w;
        s3 += q4.x * h4.x * x4.x + q4.y * h4.y * x4.y +
              q4.z * h4.z * x4.z + q4.w * h4.w * x4.w;
    }
#pragma unroll
    for (int off = 16; off > 0; off >>= 1) {
        s0 += __shfl_xor_sync(0xffffffffu, s0, off);
        s1 += __shfl_xor_sync(0xffffffffu, s1, off);
        s3 += __shfl_xor_sync(0xffffffffu, s3, off);
    }
    const float inv = rsqrtf((float)HD_);
    float sc0 = s0 * inv, sc1 = s1 * inv, sc2 = (s0 + s1) * inv, sc3 = s3 * inv;
    float m  = fmaxf(fmaxf(sc0, sc1), fmaxf(sc2, sc3));
    float e0 = expf(sc0 - m), e1 = expf(sc1 - m), e2 = expf(sc2 - m), e3 = expf(sc3 - m);
    float rs = 1.0f / (e0 + e1 + e2 + e3);
    float w0 = e0 * rs, w1 = e1 * rs, w2 = e2 * rs, w3 = e3 * rs;
    float ch = w0 + w2, cx = w1 + w2;

    __half2* op = (__half2*)(ah + base);
#pragma unroll
    for (int i = 0; i < 4; i++) {
        float4 h4 = hv[i], x4 = xv[i];
        float o0 = ch * h4.x + cx * x4.x + w3 * h4.x * x4.x;
        float o1 = ch * h4.y + cx * x4.y + w3 * h4.y * x4.y;
        float o2 = ch * h4.z + cx * x4.z + w3 * h4.z * x4.z;
        float o3 = ch * h4.w + cx * x4.w + w3 * h4.w * x4.w;
        int idx = (i * 32 + lane) * 2;
        op[idx]     = __floats2half2_rn(o0, o1);
        op[idx + 1] = __floats2half2_rn(o2, o3);
    }
}

// ---------------------------------------------------------------------------
// LayerNorm + gated mix
// ---------------------------------------------------------------------------
__global__ void __launch_bounds__(256)
ln_gate_kernel(const float* __restrict__ attn_g, const float* __restrict__ h_prev,
               const float* __restrict__ gate, const float* __restrict__ gamma,
               const float* __restrict__ beta, float* __restrict__ out)
{
    const int b   = blockIdx.x;
    const int tid = threadIdx.x;
    const size_t rb = (size_t)b * H_;

    float4 y[2], h4[2];
    float sum = 0.f, sq = 0.f;
#pragma unroll
    for (int c = 0; c < 2; c++) {
        int d = c * 1024 + tid * 4;
        float4 a  = *(const float4*)(attn_g + rb + d);
        float4 hh = *(const float4*)(h_prev + rb + d);
        float4 yy = make_float4(a.x + hh.x, a.y + hh.y, a.z + hh.z, a.w + hh.w);
        y[c] = yy; h4[c] = hh;
        sum += yy.x + yy.y + yy.z + yy.w;
        sq  += yy.x * yy.x + yy.y * yy.y + yy.z * yy.z + yy.w * yy.w;
    }
#pragma unroll
    for (int off = 16; off > 0; off >>= 1) {
        sum += __shfl_xor_sync(0xffffffffu, sum, off);
        sq  += __shfl_xor_sync(0xffffffffu, sq,  off);
    }
    __shared__ float s_sum[8], s_sq[8];
    __shared__ float s_mu, s_rstd;
    if ((tid & 31) == 0) { s_sum[tid >> 5] = sum; s_sq[tid >> 5] = sq; }
    __syncthreads();
    if (tid == 0) {
        float S = 0.f, Q = 0.f;
#pragma unroll
        for (int i = 0; i < 8; i++) { S += s_sum[i]; Q += s_sq[i]; }
        float mu  = S / (float)H_;
        float var = Q / (float)H_ - mu * mu;
        s_mu = mu;
        s_rstd = rsqrtf(var + EPS_);
    }
    __syncthreads();
    const float mu = s_mu, rstd = s_rstd;

#pragma unroll
    for (int c = 0; c < 2; c++) {
        int d = c * 1024 + tid * 4;
        float4 g4 = *(const float4*)(gate  + rb + d);
        float4 gm = *(const float4*)(gamma + d);
        float4 bt = *(const float4*)(beta  + d);
        float4 yy = y[c], hh = h4[c], o;
        float c0 = (yy.x - mu) * rstd * gm.x + bt.x;
        float c1 = (yy.y - mu) * rstd * gm.y + bt.y;
        float c2 = (yy.z - mu) * rstd * gm.z + bt.z;
        float c3 = (yy.w - mu) * rstd * gm.w + bt.w;
        o.x = g4.x * c0 + (1.0f - g4.x) * hh.x;
        o.y = g4.y * c1 + (1.0f - g4.y) * hh.y;
        o.z = g4.z * c2 + (1.0f - g4.z) * hh.z;
        o.w = g4.w * c3 + (1.0f - g4.w) * hh.w;
        *(float4*)(out + rb + d) = o;
    }
}

// ---------------------------------------------------------------------------
extern "C" void kernel_launch(void* const* d_in, const int* in_sizes, int n_in,
                              void* d_out, int out_size)
{
    const float* h_prev = (const float*)d_in[0];
    const float* x      = (const float*)d_in[1];
    const float* W_proj = (const float*)d_in[2];
    const float* b_proj = (const float*)d_in[3];
    const float* W_q    = (const float*)d_in[4];
    const float* b_q    = (const float*)d_in[5];
    const float* W_o    = (const float*)d_in[6];
    const float* b_o    = (const float*)d_in[7];
    const float* W_g    = (const float*)d_in[8];
    const float* b_g    = (const float*)d_in[9];
    const float* gamma  = (const float*)d_in[10];
    const float* beta   = (const float*)d_in[11];
    float* out = (float*)d_out;

    float *buf0, *buf1, *buf2;
    __half *xsh, *hsh, *ath, *agh;
    __half *wph, *wpl, *wqh, *wql, *woh, *wol, *wgh, *wgl;
    cudaGetSymbolAddress((void**)&buf0, g_buf0);
    cudaGetSymbolAddress((void**)&buf1, g_buf1);
    cudaGetSymbolAddress((void**)&buf2, g_buf2);
    cudaGetSymbolAddress((void**)&xsh, g_xs_h);
    cudaGetSymbolAddress((void**)&hsh, g_hs_h);
    cudaGetSymbolAddress((void**)&ath, g_at_h);
    cudaGetSymbolAddress((void**)&agh, g_ag_h);
    cudaGetSymbolAddress((void**)&wph, g_wp_hi);
    cudaGetSymbolAddress((void**)&wpl, g_wp_lo);
    cudaGetSymbolAddress((void**)&wqh, g_wq_hi);
    cudaGetSymbolAddress((void**)&wql, g_wq_lo);
    cudaGetSymbolAddress((void**)&woh, g_wo_hi);
    cudaGetSymbolAddress((void**)&wol, g_wo_lo);
    cudaGetSymbolAddress((void**)&wgh, g_wg_hi);
    cudaGetSymbolAddress((void**)&wgl, g_wg_lo);

    cudaFuncSetAttribute(gemm_mma<0, false>, cudaFuncAttributeMaxDynamicSharedMemorySize, SMEM_BYTES);
    cudaFuncSetAttribute(gemm_mma<1, true >, cudaFuncAttributeMaxDynamicSharedMemorySize, SMEM_BYTES);
    cudaFuncSetAttribute(gemm_mma<2, false>, cudaFuncAttributeMaxDynamicSharedMemorySize, SMEM_BYTES);

    // conversions
    {
        int n4;
        n4 = B_ * IN_ / 4;     split_a_kernel<<<n4 / 256, 256>>>(x, xsh, n4);
        n4 = B_ * H_ / 4;      split_a_kernel<<<n4 / 256, 256>>>(h_prev, hsh, n4);
        n4 = H_ * IN_ / 4;     split_w_kernel<<<n4 / 256, 256>>>(W_proj, wph, wpl, n4);
        n4 = H_ * H_ / 4;      split_w_kernel<<<n4 / 256, 256>>>(W_q, wqh, wql, n4);
        n4 = H_ * H_ / 4;      split_w_kernel<<<n4 / 256, 256>>>(W_o, woh, wol, n4);
        n4 = H_ * 2 * H_ / 4;  split_w_kernel<<<n4 / 256, 256>>>(W_g, wgh, wgl, n4);
    }

    dim3 grid(H_ / 256, B_ / 128);   // (8, 64)

    // 1) x_proj = x @ W_proj^T + b_proj            -> buf0
    gemm_mma<0, false><<<grid, 256, SMEM_BYTES>>>(
        xsh, xsh, IN_, wph, wpl, b_proj, buf0, nullptr, B_, H_, IN_);
    // 2) q = h_prev @ W_q^T + b_q                  -> buf1
    gemm_mma<0, false><<<grid, 256, SMEM_BYTES>>>(
        hsh, hsh, H_, wqh, wql, b_q, buf1, nullptr, B_, H_, H_);
    // 3) attention -> attn (fp16)
    attn_kernel<<<(B_ * NH_) / 8, 256>>>(h_prev, buf0, buf1, ath);
    // 4) attn_gelu = gelu(attn @ W_o^T + b_o)      -> buf2 (fp32) + fp16
    gemm_mma<1, true><<<grid, 256, SMEM_BYTES>>>(
        ath, ath, H_, woh, wol, b_o, buf2, agh, B_, H_, H_);
    // 5) gate = sigmoid([h_prev, attn_gelu] @ W_g^T + b_g) -> buf1
    gemm_mma<2, false><<<grid, 256, SMEM_BYTES>>>(
        hsh, agh, H_, wgh, wgl, b_g, buf1, nullptr, B_, H_, 2 * H_);
    // 6) layernorm + gated mix                     -> out
    ln_gate_kernel<<<B_, 256>>>(buf2, h_prev, buf1, gamma, beta, out);
}

// round 6
// speedup vs baseline: 2.2934x; 1.6369x over previous
#include <cuda_runtime.h>
#include <cuda_fp16.h>
#include <math.h>
#include <stdint.h>

#define B_  8192
#define IN_ 1024
#define H_  2048
#define NH_ 4
#define HD_ 512
#define EPS_ 1e-5f

// ---------------------------------------------------------------------------
// Device scratch (allocation-free rule)
// ---------------------------------------------------------------------------
__device__ __align__(128) float g_buf0[(size_t)B_ * H_];   // x_proj (fp32)
__device__ __align__(128) float g_buf1[(size_t)B_ * H_];   // q -> gate (fp32)
__device__ __align__(128) float g_buf2[(size_t)B_ * H_];   // attn_gelu (fp32)

// activations: fp16
__device__ __align__(128) __half g_xs_h[(size_t)B_ * IN_];
__device__ __align__(128) __half g_hs_h[(size_t)B_ * H_];
__device__ __align__(128) __half g_at_h[(size_t)B_ * H_];
__device__ __align__(128) __half g_ag_h[(size_t)B_ * H_];

// weights: fp16
__device__ __align__(128) __half g_wp_h[(size_t)H_ * IN_];
__device__ __align__(128) __half g_wq_h[(size_t)H_ * H_];
__device__ __align__(128) __half g_wo_h[(size_t)H_ * H_];
__device__ __align__(128) __half g_wg_h[(size_t)H_ * 2 * H_];

// ---------------------------------------------------------------------------
// PTX helpers (base-target-safe)
// ---------------------------------------------------------------------------
__device__ __forceinline__ uint32_t smem_u32(const void* p) {
    uint32_t a;
    asm("{ .reg .u64 t; cvta.to.shared.u64 t, %1; cvt.u32.u64 %0, t; }" : "=r"(a) : "l"(p));
    return a;
}

#define CP_ASYNC16(sa, ga) \
    asm volatile("cp.async.cg.shared.global [%0], [%1], 16;\n" :: "r"(sa), "l"(ga))
#define CP_COMMIT()  asm volatile("cp.async.commit_group;\n" ::: "memory")
#define CP_WAIT0()   asm volatile("cp.async.wait_group 0;\n" ::: "memory")
#define CP_WAIT1()   asm volatile("cp.async.wait_group 1;\n" ::: "memory")

#define LDSM_X4(r0, r1, r2, r3, addr) \
    asm volatile("ldmatrix.sync.aligned.m8n8.x4.shared.b16 {%0,%1,%2,%3}, [%4];" \
        : "=r"(r0), "=r"(r1), "=r"(r2), "=r"(r3) : "r"(addr))

#define MMA_F16(c0, c1, c2, c3, a0, a1, a2, a3, b0, b1) \
    asm volatile("mma.sync.aligned.m16n8k16.row.col.f32.f16.f16.f32 " \
        "{%0,%1,%2,%3}, {%4,%5,%6,%7}, {%8,%9}, {%0,%1,%2,%3};" \
        : "+f"(c0), "+f"(c1), "+f"(c2), "+f"(c3) \
        : "r"(a0), "r"(a1), "r"(a2), "r"(a3), "r"(b0), "r"(b1))

// ---------------------------------------------------------------------------
// SMEM: per stage: A 128x32 fp16, B 256x32 fp16, padded stride 40.
// ---------------------------------------------------------------------------
#define SSTR 40
#define A_ELEMS (128 * SSTR)               // 5120
#define BT_ELEMS (256 * SSTR)              // 10240
#define OFF_A 0
#define OFF_B A_ELEMS
#define STAGE_ELEMS (A_ELEMS + BT_ELEMS)           // 15360
#define SMEM_BYTES (2 * STAGE_ELEMS * 2)           // 61440

// ---------------------------------------------------------------------------
// fp16 GEMM on HMMA (fp32 accum):  C[M,N] = act( A @ B^T + bias )
// A logically = concat(A0[:, :Ks], A1[:, Ks:]) row-major, fp16.
// CTA tile 128x256, warp tile 64x64, K-chunk 32, 2-stage cp.async pipeline.
// ACT: 0 none, 1 exact gelu, 2 sigmoid. SPLIT_OUT also writes fp16.
// ---------------------------------------------------------------------------
template<int ACT, bool SPLIT_OUT>
__global__ void __launch_bounds__(256, 1)
gemm_mma(const __half* __restrict__ a0h, const __half* __restrict__ a1h, int Ks,
         const __half* __restrict__ bhp,
         const float* __restrict__ bias, float* __restrict__ C,
         __half* __restrict__ ohi,
         int M, int N, int K)
{
    extern __shared__ __align__(128) char smem[];
    const uint32_t sbase = smem_u32(smem);
    const int tid  = threadIdx.x;
    const int warp = tid >> 5;
    const int lane = tid & 31;
    const int bm = blockIdx.y * 128;
    const int bn = blockIdx.x * 256;
    const int wm = (warp >> 2) * 64;       // 0 or 64
    const int wn = (warp & 3) * 64;        // 0..192

    float acc[4][8][4];
#pragma unroll
    for (int i = 0; i < 4; i++)
#pragma unroll
        for (int j = 0; j < 8; j++)
#pragma unroll
            for (int r = 0; r < 4; r++) acc[i][j][r] = 0.0f;

    const int nk = K / 32;

    // ---- stage loader ----
    auto load_stage = [&](int stage, int k0) {
        const __half* ah;
        int lda, kk;
        if (k0 < Ks) { ah = a0h; lda = Ks;     kk = k0; }
        else         { ah = a1h; lda = K - Ks; kk = k0 - Ks; }
        const uint32_t stb = sbase + (uint32_t)stage * STAGE_ELEMS * 2;
#pragma unroll
        for (int r = 0; r < 2; r++) {                   // A: 512 chunks
            const int c   = tid + r * 256;
            const int row = c >> 2;
            const int seg = c & 3;
            const uint32_t so = stb + (uint32_t)(row * SSTR + seg * 8) * 2;
            const size_t ga = (size_t)(bm + row) * lda + kk + seg * 8;
            CP_ASYNC16(so + OFF_A * 2, ah + ga);
        }
#pragma unroll
        for (int r = 0; r < 4; r++) {                   // B: 1024 chunks
            const int c   = tid + r * 256;
            const int row = c >> 2;
            const int seg = c & 3;
            const uint32_t so = stb + (uint32_t)(row * SSTR + seg * 8) * 2;
            const size_t gb = (size_t)(bn + row) * K + k0 + seg * 8;
            CP_ASYNC16(so + OFF_B * 2, bhp + gb);
        }
        CP_COMMIT();
    };

    // ldmatrix lane geometry
    const int lrow = (lane & 7) + ((lane >> 3) & 1) * 8;   // 0..15
    const int lcol = (lane >> 4) * 8;                      // 0 or 8

    load_stage(0, 0);

    for (int kc = 0; kc < nk; kc++) {
        if (kc + 1 < nk) { load_stage((kc + 1) & 1, (kc + 1) * 32); CP_WAIT1(); }
        else             { CP_WAIT0(); }
        __syncthreads();

        const uint32_t stb = sbase + (uint32_t)(kc & 1) * STAGE_ELEMS * 2;
#pragma unroll
        for (int ks = 0; ks < 2; ks++) {
            const int kb = ks * 16 + lcol;
            uint32_t ah[4][4];
#pragma unroll
            for (int i = 0; i < 4; i++) {
                const uint32_t ad = stb + (uint32_t)((wm + i * 16 + lrow) * SSTR + kb) * 2;
                LDSM_X4(ah[i][0], ah[i][1], ah[i][2], ah[i][3], ad + OFF_A * 2);
            }
#pragma unroll
            for (int p = 0; p < 4; p++) {
                const uint32_t bd = stb + (uint32_t)((wn + p * 16 + lrow) * SSTR + kb) * 2;
                uint32_t h0, h1, h2, h3;
                LDSM_X4(h0, h1, h2, h3, bd + OFF_B * 2);
                const int j0 = 2 * p, j1 = 2 * p + 1;
#pragma unroll
                for (int i = 0; i < 4; i++) {
                    float* c0 = acc[i][j0];
                    float* c1 = acc[i][j1];
                    MMA_F16(c0[0], c0[1], c0[2], c0[3],
                            ah[i][0], ah[i][1], ah[i][2], ah[i][3], h0, h2);
                    MMA_F16(c1[0], c1[1], c1[2], c1[3],
                            ah[i][0], ah[i][1], ah[i][2], ah[i][3], h1, h3);
                }
            }
        }
        __syncthreads();
    }

    // ---- epilogue: bias + activation (+ optional fp16 out) ----
    const int tr = lane >> 2;
    const int tc = (lane & 3) * 2;
#pragma unroll
    for (int i = 0; i < 4; i++) {
        const int r0 = bm + wm + i * 16 + tr;
        const int r1 = r0 + 8;
#pragma unroll
        for (int j = 0; j < 8; j++) {
            const int col = bn + wn + j * 8 + tc;
            const float b0 = bias[col], b1 = bias[col + 1];
            float v[4] = {acc[i][j][0] + b0, acc[i][j][1] + b1,
                          acc[i][j][2] + b0, acc[i][j][3] + b1};
#pragma unroll
            for (int r = 0; r < 4; r++) {
                if (ACT == 1)      v[r] = 0.5f * v[r] * (1.0f + erff(v[r] * 0.70710678118654752f));
                else if (ACT == 2) v[r] = 1.0f / (1.0f + expf(-v[r]));
            }
            *(float2*)(C + (size_t)r0 * N + col) = make_float2(v[0], v[1]);
            *(float2*)(C + (size_t)r1 * N + col) = make_float2(v[2], v[3]);
            if (SPLIT_OUT) {
                *(__half2*)(ohi + (size_t)r0 * N + col) =
                    __floats2half2_rn(v[0], v[1]);
                *(__half2*)(ohi + (size_t)r1 * N + col) =
                    __floats2half2_rn(v[2], v[3]);
            }
        }
    }
}

// ---------------------------------------------------------------------------
// fp32 -> fp16 conversion
// ---------------------------------------------------------------------------
__global__ void __launch_bounds__(256)
cvt_kernel(const float* __restrict__ in, __half* __restrict__ hi, int n4)
{
    int i = blockIdx.x * 256 + threadIdx.x;
    if (i >= n4) return;
    float4 v = ((const float4*)in)[i];
    ((__half2*)hi)[2*i]   = __floats2half2_rn(v.x, v.y);
    ((__half2*)hi)[2*i+1] = __floats2half2_rn(v.z, v.w);
}

// ---------------------------------------------------------------------------
// 4-key attention; writes attn as fp16.
// ---------------------------------------------------------------------------
__global__ void __launch_bounds__(256)
attn_kernel(const float* __restrict__ h_prev, const float* __restrict__ xproj,
            const float* __restrict__ q, __half* __restrict__ ah)
{
    const int gw   = (blockIdx.x * 256 + threadIdx.x) >> 5;
    const int lane = threadIdx.x & 31;
    if (gw >= B_ * NH_) return;
    const size_t base = (size_t)(gw / NH_) * H_ + (size_t)(gw % NH_) * HD_;

    const float4* qp = (const float4*)(q + base);
    const float4* hp = (const float4*)(h_prev + base);
    const float4* xp = (const float4*)(xproj + base);

    float s0 = 0.f, s1 = 0.f, s3 = 0.f;
    float4 hv[4], xv[4];
#pragma unroll
    for (int i = 0; i < 4; i++) {
        float4 q4 = qp[i * 32 + lane];
        float4 h4 = hp[i * 32 + lane];
        float4 x4 = xp[i * 32 + lane];
        hv[i] = h4; xv[i] = x4;
        s0 += q4.x * h4.x + q4.y * h4.y + q4.z * h4.z + q4.w * h4.w;
        s1 += q4.x * x4.x + q4.y * x4.y + q4.z * x4.z + q4.w * x4.w;
        s3 += q4.x * h4.x * x4.x + q4.y * h4.y * x4.y +
              q4.z * h4.z * x4.z + q4.w * h4.w * x4.w;
    }
#pragma unroll
    for (int off = 16; off > 0; off >>= 1) {
        s0 += __shfl_xor_sync(0xffffffffu, s0, off);
        s1 += __shfl_xor_sync(0xffffffffu, s1, off);
        s3 += __shfl_xor_sync(0xffffffffu, s3, off);
    }
    const float inv = rsqrtf((float)HD_);
    float sc0 = s0 * inv, sc1 = s1 * inv, sc2 = (s0 + s1) * inv, sc3 = s3 * inv;
    float m  = fmaxf(fmaxf(sc0, sc1), fmaxf(sc2, sc3));
    float e0 = expf(sc0 - m), e1 = expf(sc1 - m), e2 = expf(sc2 - m), e3 = expf(sc3 - m);
    float rs = 1.0f / (e0 + e1 + e2 + e3);
    float w0 = e0 * rs, w1 = e1 * rs, w2 = e2 * rs, w3 = e3 * rs;
    float ch = w0 + w2, cx = w1 + w2;

    __half2* op = (__half2*)(ah + base);
#pragma unroll
    for (int i = 0; i < 4; i++) {
        float4 h4 = hv[i], x4 = xv[i];
        float o0 = ch * h4.x + cx * x4.x + w3 * h4.x * x4.x;
        float o1 = ch * h4.y + cx * x4.y + w3 * h4.y * x4.y;
        float o2 = ch * h4.z + cx * x4.z + w3 * h4.z * x4.z;
        float o3 = ch * h4.w + cx * x4.w + w3 * h4.w * x4.w;
        int idx = (i * 32 + lane) * 2;
        op[idx]     = __floats2half2_rn(o0, o1);
        op[idx + 1] = __floats2half2_rn(o2, o3);
    }
}

// ---------------------------------------------------------------------------
// LayerNorm + gated mix
// ---------------------------------------------------------------------------
__global__ void __launch_bounds__(256)
ln_gate_kernel(const float* __restrict__ attn_g, const float* __restrict__ h_prev,
               const float* __restrict__ gate, const float* __restrict__ gamma,
               const float* __restrict__ beta, float* __restrict__ out)
{
    const int b   = blockIdx.x;
    const int tid = threadIdx.x;
    const size_t rb = (size_t)b * H_;

    float4 y[2], h4[2];
    float sum = 0.f, sq = 0.f;
#pragma unroll
    for (int c = 0; c < 2; c++) {
        int d = c * 1024 + tid * 4;
        float4 a  = *(const float4*)(attn_g + rb + d);
        float4 hh = *(const float4*)(h_prev + rb + d);
        float4 yy = make_float4(a.x + hh.x, a.y + hh.y, a.z + hh.z, a.w + hh.w);
        y[c] = yy; h4[c] = hh;
        sum += yy.x + yy.y + yy.z + yy.w;
        sq  += yy.x * yy.x + yy.y * yy.y + yy.z * yy.z + yy.w * yy.w;
    }
#pragma unroll
    for (int off = 16; off > 0; off >>= 1) {
        sum += __shfl_xor_sync(0xffffffffu, sum, off);
        sq  += __shfl_xor_sync(0xffffffffu, sq,  off);
    }
    __shared__ float s_sum[8], s_sq[8];
    __shared__ float s_mu, s_rstd;
    if ((tid & 31) == 0) { s_sum[tid >> 5] = sum; s_sq[tid >> 5] = sq; }
    __syncthreads();
    if (tid == 0) {
        float S = 0.f, Q = 0.f;
#pragma unroll
        for (int i = 0; i < 8; i++) { S += s_sum[i]; Q += s_sq[i]; }
        float mu  = S / (float)H_;
        float var = Q / (float)H_ - mu * mu;
        s_mu = mu;
        s_rstd = rsqrtf(var + EPS_);
    }
    __syncthreads();
    const float mu = s_mu, rstd = s_rstd;

#pragma unroll
    for (int c = 0; c < 2; c++) {
        int d = c * 1024 + tid * 4;
        float4 g4 = *(const float4*)(gate  + rb + d);
        float4 gm = *(const float4*)(gamma + d);
        float4 bt = *(const float4*)(beta  + d);
        float4 yy = y[c], hh = h4[c], o;
        float c0 = (yy.x - mu) * rstd * gm.x + bt.x;
        float c1 = (yy.y - mu) * rstd * gm.y + bt.y;
        float c2 = (yy.z - mu) * rstd * gm.z + bt.z;
        float c3 = (yy.w - mu) * rstd * gm.w + bt.w;
        o.x = g4.x * c0 + (1.0f - g4.x) * hh.x;
        o.y = g4.y * c1 + (1.0f - g4.y) * hh.y;
        o.z = g4.z * c2 + (1.0f - g4.z) * hh.z;
        o.w = g4.w * c3 + (1.0f - g4.w) * hh.w;
        *(float4*)(out + rb + d) = o;
    }
}

// ---------------------------------------------------------------------------
extern "C" void kernel_launch(void* const* d_in, const int* in_sizes, int n_in,
                              void* d_out, int out_size)
{
    const float* h_prev = (const float*)d_in[0];
    const float* x      = (const float*)d_in[1];
    const float* W_proj = (const float*)d_in[2];
    const float* b_proj = (const float*)d_in[3];
    const float* W_q    = (const float*)d_in[4];
    const float* b_q    = (const float*)d_in[5];
    const float* W_o    = (const float*)d_in[6];
    const float* b_o    = (const float*)d_in[7];
    const float* W_g    = (const float*)d_in[8];
    const float* b_g    = (const float*)d_in[9];
    const float* gamma  = (const float*)d_in[10];
    const float* beta   = (const float*)d_in[11];
    float* out = (float*)d_out;

    float *buf0, *buf1, *buf2;
    __half *xsh, *hsh, *ath, *agh;
    __half *wph, *wqh, *woh, *wgh;
    cudaGetSymbolAddress((void**)&buf0, g_buf0);
    cudaGetSymbolAddress((void**)&buf1, g_buf1);
    cudaGetSymbolAddress((void**)&buf2, g_buf2);
    cudaGetSymbolAddress((void**)&xsh, g_xs_h);
    cudaGetSymbolAddress((void**)&hsh, g_hs_h);
    cudaGetSymbolAddress((void**)&ath, g_at_h);
    cudaGetSymbolAddress((void**)&agh, g_ag_h);
    cudaGetSymbolAddress((void**)&wph, g_wp_h);
    cudaGetSymbolAddress((void**)&wqh, g_wq_h);
    cudaGetSymbolAddress((void**)&woh, g_wo_h);
    cudaGetSymbolAddress((void**)&wgh, g_wg_h);

    cudaFuncSetAttribute(gemm_mma<0, false>, cudaFuncAttributeMaxDynamicSharedMemorySize, SMEM_BYTES);
    cudaFuncSetAttribute(gemm_mma<1, true >, cudaFuncAttributeMaxDynamicSharedMemorySize, SMEM_BYTES);
    cudaFuncSetAttribute(gemm_mma<2, false>, cudaFuncAttributeMaxDynamicSharedMemorySize, SMEM_BYTES);

    // conversions
    {
        int n4;
        n4 = B_ * IN_ / 4;     cvt_kernel<<<n4 / 256, 256>>>(x, xsh, n4);
        n4 = B_ * H_ / 4;      cvt_kernel<<<n4 / 256, 256>>>(h_prev, hsh, n4);
        n4 = H_ * IN_ / 4;     cvt_kernel<<<n4 / 256, 256>>>(W_proj, wph, n4);
        n4 = H_ * H_ / 4;      cvt_kernel<<<n4 / 256, 256>>>(W_q, wqh, n4);
        n4 = H_ * H_ / 4;      cvt_kernel<<<n4 / 256, 256>>>(W_o, woh, n4);
        n4 = H_ * 2 * H_ / 4;  cvt_kernel<<<n4 / 256, 256>>>(W_g, wgh, n4);
    }

    dim3 grid(H_ / 256, B_ / 128);   // (8, 64)

    // 1) x_proj = x @ W_proj^T + b_proj            -> buf0
    gemm_mma<0, false><<<grid, 256, SMEM_BYTES>>>(
        xsh, xsh, IN_, wph, b_proj, buf0, nullptr, B_, H_, IN_);
    // 2) q = h_prev @ W_q^T + b_q                  -> buf1
    gemm_mma<0, false><<<grid, 256, SMEM_BYTES>>>(
        hsh, hsh, H_, wqh, b_q, buf1, nullptr, B_, H_, H_);
    // 3) attention -> attn (fp16)
    attn_kernel<<<(B_ * NH_) / 8, 256>>>(h_prev, buf0, buf1, ath);
    // 4) attn_gelu = gelu(attn @ W_o^T + b_o)      -> buf2 (fp32) + fp16
    gemm_mma<1, true><<<grid, 256, SMEM_BYTES>>>(
        ath, ath, H_, woh, b_o, buf2, agh, B_, H_, H_);
    // 5) gate = sigmoid([h_prev, attn_gelu] @ W_g^T + b_g) -> buf1
    gemm_mma<2, false><<<grid, 256, SMEM_BYTES>>>(
        hsh, agh, H_, wgh, b_g, buf1, nullptr, B_, H_, 2 * H_);
    // 6) layernorm + gated mix                     -> out
    ln_gate_kernel<<<B_, 256>>>(buf2, h_prev, buf1, gamma, beta, out);
}

// round 7
// speedup vs baseline: 2.6978x; 1.1764x over previous
#include <cuda_runtime.h>
#include <cuda_fp16.h>
#include <math.h>
#include <stdint.h>

#define B_  8192
#define IN_ 1024
#define H_  2048
#define NH_ 4
#define HD_ 512
#define EPS_ 1e-5f

// ---------------------------------------------------------------------------
// Device scratch (allocation-free rule)
// ---------------------------------------------------------------------------
__device__ __align__(128) float g_buf1[(size_t)B_ * H_];   // gate (fp32)
__device__ __align__(128) float g_buf2[(size_t)B_ * H_];   // attn_gelu (fp32)

// fp16 activations / intermediates
__device__ __align__(128) __half g_xs_h[(size_t)B_ * IN_];   // x fp16
__device__ __align__(128) __half g_hs_h[(size_t)B_ * H_];    // h_prev fp16
__device__ __align__(128) __half g_xp_h[(size_t)B_ * H_];    // x_proj fp16
__device__ __align__(128) __half g_q_h [(size_t)B_ * H_];    // q fp16
__device__ __align__(128) __half g_at_h[(size_t)B_ * H_];    // attn fp16
__device__ __align__(128) __half g_ag_h[(size_t)B_ * H_];    // attn_gelu fp16

// fp16 weights
__device__ __align__(128) __half g_wp_h[(size_t)H_ * IN_];
__device__ __align__(128) __half g_wq_h[(size_t)H_ * H_];
__device__ __align__(128) __half g_wo_h[(size_t)H_ * H_];
__device__ __align__(128) __half g_wg_h[(size_t)H_ * 2 * H_];

// ---------------------------------------------------------------------------
// PTX helpers (base-target-safe)
// ---------------------------------------------------------------------------
__device__ __forceinline__ uint32_t smem_u32(const void* p) {
    uint32_t a;
    asm("{ .reg .u64 t; cvta.to.shared.u64 t, %1; cvt.u32.u64 %0, t; }" : "=r"(a) : "l"(p));
    return a;
}

#define CP_ASYNC16(sa, ga) \
    asm volatile("cp.async.cg.shared.global [%0], [%1], 16;\n" :: "r"(sa), "l"(ga))
#define CP_COMMIT()  asm volatile("cp.async.commit_group;\n" ::: "memory")
#define CP_WAIT0()   asm volatile("cp.async.wait_group 0;\n" ::: "memory")
#define CP_WAIT1()   asm volatile("cp.async.wait_group 1;\n" ::: "memory")

#define LDSM_X4(r0, r1, r2, r3, addr) \
    asm volatile("ldmatrix.sync.aligned.m8n8.x4.shared.b16 {%0,%1,%2,%3}, [%4];" \
        : "=r"(r0), "=r"(r1), "=r"(r2), "=r"(r3) : "r"(addr))

#define MMA_F16(c0, c1, c2, c3, a0, a1, a2, a3, b0, b1) \
    asm volatile("mma.sync.aligned.m16n8k16.row.col.f32.f16.f16.f32 " \
        "{%0,%1,%2,%3}, {%4,%5,%6,%7}, {%8,%9}, {%0,%1,%2,%3};" \
        : "+f"(c0), "+f"(c1), "+f"(c2), "+f"(c3) \
        : "r"(a0), "r"(a1), "r"(a2), "r"(a3), "r"(b0), "r"(b1))

// ---------------------------------------------------------------------------
// SMEM: per stage: A 128x32 fp16, B 128x32 fp16, padded stride 40.
// Total 40 KB -> 2 CTAs/SM feasible.
// ---------------------------------------------------------------------------
#define SSTR 40
#define A_ELEMS (128 * SSTR)               // 5120
#define OFF_A 0
#define OFF_B A_ELEMS
#define STAGE_ELEMS (2 * A_ELEMS)          // 10240
#define SMEM_BYTES (2 * STAGE_ELEMS * 2)   // 40960

// ---------------------------------------------------------------------------
// fp16 GEMM on HMMA (fp32 accum):  C[M,N] = act( A @ B^T + bias )
// A logically = concat(A0[:, :Ks], A1[:, Ks:]) row-major, fp16.
// CTA tile 128x128, warp tile 64x32, K-chunk 32, 2-stage cp.async pipeline.
// ACT: 0 none, 1 exact gelu, 2 sigmoid.
// OUTMODE: 0 = fp32 only, 1 = fp32 + fp16, 2 = fp16 only.
// ---------------------------------------------------------------------------
template<int ACT, int OUTMODE>
__global__ void __launch_bounds__(256, 2)
gemm_mma(const __half* __restrict__ a0h, const __half* __restrict__ a1h, int Ks,
         const __half* __restrict__ bhp,
         const float* __restrict__ bias, float* __restrict__ C,
         __half* __restrict__ ohi,
         int M, int N, int K)
{
    extern __shared__ __align__(128) char smem[];
    const uint32_t sbase = smem_u32(smem);
    const int tid  = threadIdx.x;
    const int warp = tid >> 5;
    const int lane = tid & 31;
    const int bm = blockIdx.y * 128;
    const int bn = blockIdx.x * 128;
    const int wm = (warp >> 2) * 64;       // 0 or 64
    const int wn = (warp & 3) * 32;        // 0..96

    float acc[4][4][4];
#pragma unroll
    for (int i = 0; i < 4; i++)
#pragma unroll
        for (int j = 0; j < 4; j++)
#pragma unroll
            for (int r = 0; r < 4; r++) acc[i][j][r] = 0.0f;

    const int nk = K / 32;

    // ---- stage loader: 2 chunks/thread each for A and B ----
    auto load_stage = [&](int stage, int k0) {
        const __half* ah;
        int lda, kk;
        if (k0 < Ks) { ah = a0h; lda = Ks;     kk = k0; }
        else         { ah = a1h; lda = K - Ks; kk = k0 - Ks; }
        const uint32_t stb = sbase + (uint32_t)stage * STAGE_ELEMS * 2;
#pragma unroll
        for (int r = 0; r < 2; r++) {
            const int c   = tid + r * 256;        // 0..511
            const int row = c >> 2;
            const int seg = c & 3;
            const uint32_t so = stb + (uint32_t)(row * SSTR + seg * 8) * 2;
            CP_ASYNC16(so + OFF_A * 2, ah  + (size_t)(bm + row) * lda + kk + seg * 8);
            CP_ASYNC16(so + OFF_B * 2, bhp + (size_t)(bn + row) * K   + k0 + seg * 8);
        }
        CP_COMMIT();
    };

    // ldmatrix lane geometry
    const int lrow = (lane & 7) + ((lane >> 3) & 1) * 8;   // 0..15
    const int lcol = (lane >> 4) * 8;                      // 0 or 8

    load_stage(0, 0);

    for (int kc = 0; kc < nk; kc++) {
        if (kc + 1 < nk) { load_stage((kc + 1) & 1, (kc + 1) * 32); CP_WAIT1(); }
        else             { CP_WAIT0(); }
        __syncthreads();

        const uint32_t stb = sbase + (uint32_t)(kc & 1) * STAGE_ELEMS * 2;
#pragma unroll
        for (int ks = 0; ks < 2; ks++) {
            const int kb = ks * 16 + lcol;
            uint32_t ah[4][4];
#pragma unroll
            for (int i = 0; i < 4; i++) {
                const uint32_t ad = stb + (uint32_t)((wm + i * 16 + lrow) * SSTR + kb) * 2;
                LDSM_X4(ah[i][0], ah[i][1], ah[i][2], ah[i][3], ad + OFF_A * 2);
            }
#pragma unroll
            for (int p = 0; p < 2; p++) {
                const uint32_t bd = stb + (uint32_t)((wn + p * 16 + lrow) * SSTR + kb) * 2;
                uint32_t b0, b1, b2, b3;
                LDSM_X4(b0, b1, b2, b3, bd + OFF_B * 2);
                const int j0 = 2 * p, j1 = 2 * p + 1;
#pragma unroll
                for (int i = 0; i < 4; i++) {
                    float* c0 = acc[i][j0];
                    float* c1 = acc[i][j1];
                    MMA_F16(c0[0], c0[1], c0[2], c0[3],
                            ah[i][0], ah[i][1], ah[i][2], ah[i][3], b0, b2);
                    MMA_F16(c1[0], c1[1], c1[2], c1[3],
                            ah[i][0], ah[i][1], ah[i][2], ah[i][3], b1, b3);
                }
            }
        }
        __syncthreads();
    }

    // ---- epilogue: bias + activation; fp32 and/or fp16 stores ----
    const int tr = lane >> 2;
    const int tc = (lane & 3) * 2;
#pragma unroll
    for (int i = 0; i < 4; i++) {
        const int r0 = bm + wm + i * 16 + tr;
        const int r1 = r0 + 8;
#pragma unroll
        for (int j = 0; j < 4; j++) {
            const int col = bn + wn + j * 8 + tc;
            const float b0 = bias[col], b1 = bias[col + 1];
            float v[4] = {acc[i][j][0] + b0, acc[i][j][1] + b1,
                          acc[i][j][2] + b0, acc[i][j][3] + b1};
#pragma unroll
            for (int r = 0; r < 4; r++) {
                if (ACT == 1)      v[r] = 0.5f * v[r] * (1.0f + erff(v[r] * 0.70710678118654752f));
                else if (ACT == 2) v[r] = 1.0f / (1.0f + expf(-v[r]));
            }
            if (OUTMODE != 2) {
                *(float2*)(C + (size_t)r0 * N + col) = make_float2(v[0], v[1]);
                *(float2*)(C + (size_t)r1 * N + col) = make_float2(v[2], v[3]);
            }
            if (OUTMODE != 0) {
                *(__half2*)(ohi + (size_t)r0 * N + col) = __floats2half2_rn(v[0], v[1]);
                *(__half2*)(ohi + (size_t)r1 * N + col) = __floats2half2_rn(v[2], v[3]);
            }
        }
    }
}

// ---------------------------------------------------------------------------
// fused fp32 -> fp16 conversion over up to 4 buffers (sizes in float4 units)
// ---------------------------------------------------------------------------
__global__ void __launch_bounds__(256)
cvt4_kernel(const float* __restrict__ i0, __half* __restrict__ o0, int n0,
            const float* __restrict__ i1, __half* __restrict__ o1, int n1,
            const float* __restrict__ i2, __half* __restrict__ o2, int n2,
            const float* __restrict__ i3, __half* __restrict__ o3, int n3)
{
    int t = blockIdx.x * 256 + threadIdx.x;
    const float* in; __half* out;
    if      (t < n0)               { in = i0; out = o0; }
    else if (t < n0 + n1)          { t -= n0;            in = i1; out = o1; }
    else if (t < n0 + n1 + n2)     { t -= n0 + n1;       in = i2; out = o2; }
    else if (t < n0 + n1 + n2 + n3){ t -= n0 + n1 + n2;  in = i3; out = o3; }
    else return;
    float4 v = ((const float4*)in)[t];
    ((__half2*)out)[2 * t]     = __floats2half2_rn(v.x, v.y);
    ((__half2*)out)[2 * t + 1] = __floats2half2_rn(v.z, v.w);
}

// ---------------------------------------------------------------------------
// 4-key attention; reads x_proj/q fp16, h fp32; writes attn fp16.
// One warp per (b, head); each lane owns 16 contiguous dims.
// ---------------------------------------------------------------------------
__global__ void __launch_bounds__(256)
attn_kernel(const float* __restrict__ h_prev, const __half* __restrict__ xproj,
            const __half* __restrict__ q, __half* __restrict__ ah)
{
    const int gw   = (blockIdx.x * 256 + threadIdx.x) >> 5;
    const int lane = threadIdx.x & 31;
    if (gw >= B_ * NH_) return;
    const size_t base = (size_t)(gw / NH_) * H_ + (size_t)(gw % NH_) * HD_ + lane * 16;

    const float4* hp = (const float4*)(h_prev + base);
    const uint4*  xp = (const uint4*)(xproj + base);
    const uint4*  qp = (const uint4*)(q + base);

    float hf[16], xf[16], qf[16];
#pragma unroll
    for (int k = 0; k < 4; k++) {
        float4 h4 = hp[k];
        hf[4*k] = h4.x; hf[4*k+1] = h4.y; hf[4*k+2] = h4.z; hf[4*k+3] = h4.w;
    }
#pragma unroll
    for (int k = 0; k < 2; k++) {
        uint4 u = xp[k];
        const __half2* p = (const __half2*)&u;
#pragma unroll
        for (int m = 0; m < 4; m++) {
            float2 t = __half22float2(p[m]);
            xf[8*k + 2*m] = t.x; xf[8*k + 2*m + 1] = t.y;
        }
        uint4 uq = qp[k];
        const __half2* pq = (const __half2*)&uq;
#pragma unroll
        for (int m = 0; m < 4; m++) {
            float2 t = __half22float2(pq[m]);
            qf[8*k + 2*m] = t.x; qf[8*k + 2*m + 1] = t.y;
        }
    }

    float s0 = 0.f, s1 = 0.f, s3 = 0.f;
#pragma unroll
    for (int k = 0; k < 16; k++) {
        s0 += qf[k] * hf[k];
        s1 += qf[k] * xf[k];
        s3 += qf[k] * hf[k] * xf[k];
    }
#pragma unroll
    for (int off = 16; off > 0; off >>= 1) {
        s0 += __shfl_xor_sync(0xffffffffu, s0, off);
        s1 += __shfl_xor_sync(0xffffffffu, s1, off);
        s3 += __shfl_xor_sync(0xffffffffu, s3, off);
    }
    const float inv = rsqrtf((float)HD_);
    float sc0 = s0 * inv, sc1 = s1 * inv, sc2 = (s0 + s1) * inv, sc3 = s3 * inv;
    float m  = fmaxf(fmaxf(sc0, sc1), fmaxf(sc2, sc3));
    float e0 = expf(sc0 - m), e1 = expf(sc1 - m), e2 = expf(sc2 - m), e3 = expf(sc3 - m);
    float rs = 1.0f / (e0 + e1 + e2 + e3);
    float w0 = e0 * rs, w1 = e1 * rs, w2 = e2 * rs, w3 = e3 * rs;
    float ch = w0 + w2, cx = w1 + w2;

    __half2 oh[8];
#pragma unroll
    for (int k = 0; k < 8; k++) {
        float o0 = ch * hf[2*k]   + cx * xf[2*k]   + w3 * hf[2*k]   * xf[2*k];
        float o1 = ch * hf[2*k+1] + cx * xf[2*k+1] + w3 * hf[2*k+1] * xf[2*k+1];
        oh[k] = __floats2half2_rn(o0, o1);
    }
    uint4* op = (uint4*)(ah + base);
    op[0] = *(uint4*)&oh[0];
    op[1] = *(uint4*)&oh[4];
}

// ---------------------------------------------------------------------------
// LayerNorm + gated mix
// ---------------------------------------------------------------------------
__global__ void __launch_bounds__(256)
ln_gate_kernel(const float* __restrict__ attn_g, const float* __restrict__ h_prev,
               const float* __restrict__ gate, const float* __restrict__ gamma,
               const float* __restrict__ beta, float* __restrict__ out)
{
    const int b   = blockIdx.x;
    const int tid = threadIdx.x;
    const size_t rb = (size_t)b * H_;

    float4 y[2], h4[2];
    float sum = 0.f, sq = 0.f;
#pragma unroll
    for (int c = 0; c < 2; c++) {
        int d = c * 1024 + tid * 4;
        float4 a  = *(const float4*)(attn_g + rb + d);
        float4 hh = *(const float4*)(h_prev + rb + d);
        float4 yy = make_float4(a.x + hh.x, a.y + hh.y, a.z + hh.z, a.w + hh.w);
        y[c] = yy; h4[c] = hh;
        sum += yy.x + yy.y + yy.z + yy.w;
        sq  += yy.x * yy.x + yy.y * yy.y + yy.z * yy.z + yy.w * yy.w;
    }
#pragma unroll
    for (int off = 16; off > 0; off >>= 1) {
        sum += __shfl_xor_sync(0xffffffffu, sum, off);
        sq  += __shfl_xor_sync(0xffffffffu, sq,  off);
    }
    __shared__ float s_sum[8], s_sq[8];
    __shared__ float s_mu, s_rstd;
    if ((tid & 31) == 0) { s_sum[tid >> 5] = sum; s_sq[tid >> 5] = sq; }
    __syncthreads();
    if (tid == 0) {
        float S = 0.f, Q = 0.f;
#pragma unroll
        for (int i = 0; i < 8; i++) { S += s_sum[i]; Q += s_sq[i]; }
        float mu  = S / (float)H_;
        float var = Q / (float)H_ - mu * mu;
        s_mu = mu;
        s_rstd = rsqrtf(var + EPS_);
    }
    __syncthreads();
    const float mu = s_mu, rstd = s_rstd;

#pragma unroll
    for (int c = 0; c < 2; c++) {
        int d = c * 1024 + tid * 4;
        float4 g4 = *(const float4*)(gate  + rb + d);
        float4 gm = *(const float4*)(gamma + d);
        float4 bt = *(const float4*)(beta  + d);
        float4 yy = y[c], hh = h4[c], o;
        float c0 = (yy.x - mu) * rstd * gm.x + bt.x;
        float c1 = (yy.y - mu) * rstd * gm.y + bt.y;
        float c2 = (yy.z - mu) * rstd * gm.z + bt.z;
        float c3 = (yy.w - mu) * rstd * gm.w + bt.w;
        o.x = g4.x * c0 + (1.0f - g4.x) * hh.x;
        o.y = g4.y * c1 + (1.0f - g4.y) * hh.y;
        o.z = g4.z * c2 + (1.0f - g4.z) * hh.z;
        o.w = g4.w * c3 + (1.0f - g4.w) * hh.w;
        *(float4*)(out + rb + d) = o;
    }
}

// ---------------------------------------------------------------------------
extern "C" void kernel_launch(void* const* d_in, const int* in_sizes, int n_in,
                              void* d_out, int out_size)
{
    const float* h_prev = (const float*)d_in[0];
    const float* x      = (const float*)d_in[1];
    const float* W_proj = (const float*)d_in[2];
    const float* b_proj = (const float*)d_in[3];
    const float* W_q    = (const float*)d_in[4];
    const float* b_q    = (const float*)d_in[5];
    const float* W_o    = (const float*)d_in[6];
    const float* b_o    = (const float*)d_in[7];
    const float* W_g    = (const float*)d_in[8];
    const float* b_g    = (const float*)d_in[9];
    const float* gamma  = (const float*)d_in[10];
    const float* beta   = (const float*)d_in[11];
    float* out = (float*)d_out;

    float *buf1, *buf2;
    __half *xsh, *hsh, *xph, *qh, *ath, *agh;
    __half *wph, *wqh, *woh, *wgh;
    cudaGetSymbolAddress((void**)&buf1, g_buf1);
    cudaGetSymbolAddress((void**)&buf2, g_buf2);
    cudaGetSymbolAddress((void**)&xsh, g_xs_h);
    cudaGetSymbolAddress((void**)&hsh, g_hs_h);
    cudaGetSymbolAddress((void**)&xph, g_xp_h);
    cudaGetSymbolAddress((void**)&qh,  g_q_h);
    cudaGetSymbolAddress((void**)&ath, g_at_h);
    cudaGetSymbolAddress((void**)&agh, g_ag_h);
    cudaGetSymbolAddress((void**)&wph, g_wp_h);
    cudaGetSymbolAddress((void**)&wqh, g_wq_h);
    cudaGetSymbolAddress((void**)&woh, g_wo_h);
    cudaGetSymbolAddress((void**)&wgh, g_wg_h);

    // --- launch #0: weight conversions (fused) ---
    {
        int n0 = H_ * IN_ / 4;       // W_proj
        int n1 = H_ * H_ / 4;        // W_q
        int n2 = H_ * H_ / 4;        // W_o
        int n3 = H_ * 2 * H_ / 4;    // W_g
        int nt = n0 + n1 + n2 + n3;
        cvt4_kernel<<<(nt + 255) / 256, 256>>>(
            W_proj, wph, n0, W_q, wqh, n1, W_o, woh, n2, W_g, wgh, n3);
    }
    // --- launch #1: activation conversions (fused) ---
    {
        int n0 = B_ * IN_ / 4;       // x
        int n1 = B_ * H_ / 4;        // h_prev
        int nt = n0 + n1;
        cvt4_kernel<<<(nt + 255) / 256, 256>>>(
            x, xsh, n0, h_prev, hsh, n1, x, xsh, 0, x, xsh, 0);
    }

    dim3 grid(H_ / 128, B_ / 128);   // (16, 64) = 1024 CTAs

    // #2) x_proj (fp16 only)
    gemm_mma<0, 2><<<grid, 256, SMEM_BYTES>>>(
        xsh, xsh, IN_, wph, b_proj, nullptr, xph, B_, H_, IN_);
    // #3) q (fp16 only)
    gemm_mma<0, 2><<<grid, 256, SMEM_BYTES>>>(
        hsh, hsh, H_, wqh, b_q, nullptr, qh, B_, H_, H_);
    // #4) attention -> attn fp16
    attn_kernel<<<(B_ * NH_) / 8, 256>>>(h_prev, xph, qh, ath);
    // #5) attn_gelu (fp32 + fp16)   <- profiled by ncu -s 5
    gemm_mma<1, 1><<<grid, 256, SMEM_BYTES>>>(
        ath, ath, H_, woh, b_o, buf2, agh, B_, H_, H_);
    // #6) gate (fp32)
    gemm_mma<2, 0><<<grid, 256, SMEM_BYTES>>>(
        hsh, agh, H_, wgh, b_g, buf1, nullptr, B_, H_, 2 * H_);
    // #7) layernorm + gated mix
    ln_gate_kernel<<<B_, 256>>>(buf2, h_prev, buf1, gamma, beta, out);
}

// round 8
// speedup vs baseline: 2.7917x; 1.0348x over previous
#include <cuda_runtime.h>
#include <cuda_fp16.h>
#include <math.h>
#include <stdint.h>

#define B_  8192
#define IN_ 1024
#define H_  2048
#define NH_ 4
#define HD_ 512
#define EPS_ 1e-5f

// ---------------------------------------------------------------------------
// Device scratch (allocation-free rule)
// ---------------------------------------------------------------------------
__device__ __align__(128) float g_buf2[(size_t)B_ * H_];   // attn_gelu (fp32)

// fp16 activations / intermediates
__device__ __align__(128) __half g_xs_h[(size_t)B_ * IN_];   // x fp16
__device__ __align__(128) __half g_hs_h[(size_t)B_ * H_];    // h_prev fp16
__device__ __align__(128) __half g_xp_h[(size_t)B_ * H_];    // x_proj fp16
__device__ __align__(128) __half g_q_h [(size_t)B_ * H_];    // q fp16 -> gate fp16
__device__ __align__(128) __half g_at_h[(size_t)B_ * H_];    // attn fp16
__device__ __align__(128) __half g_ag_h[(size_t)B_ * H_];    // attn_gelu fp16

// fp16 weights
__device__ __align__(128) __half g_wp_h[(size_t)H_ * IN_];
__device__ __align__(128) __half g_wq_h[(size_t)H_ * H_];
__device__ __align__(128) __half g_wo_h[(size_t)H_ * H_];
__device__ __align__(128) __half g_wg_h[(size_t)H_ * 2 * H_];

// ---------------------------------------------------------------------------
// PTX helpers (base-target-safe)
// ---------------------------------------------------------------------------
__device__ __forceinline__ uint32_t smem_u32(const void* p) {
    uint32_t a;
    asm("{ .reg .u64 t; cvta.to.shared.u64 t, %1; cvt.u32.u64 %0, t; }" : "=r"(a) : "l"(p));
    return a;
}

#define CP_ASYNC16(sa, ga) \
    asm volatile("cp.async.cg.shared.global [%0], [%1], 16;\n" :: "r"(sa), "l"(ga))
#define CP_COMMIT()  asm volatile("cp.async.commit_group;\n" ::: "memory")

#define LDSM_X4(r0, r1, r2, r3, addr) \
    asm volatile("ldmatrix.sync.aligned.m8n8.x4.shared.b16 {%0,%1,%2,%3}, [%4];" \
        : "=r"(r0), "=r"(r1), "=r"(r2), "=r"(r3) : "r"(addr))

#define MMA_F16(c0, c1, c2, c3, a0, a1, a2, a3, b0, b1) \
    asm volatile("mma.sync.aligned.m16n8k16.row.col.f32.f16.f16.f32 " \
        "{%0,%1,%2,%3}, {%4,%5,%6,%7}, {%8,%9}, {%0,%1,%2,%3};" \
        : "+f"(c0), "+f"(c1), "+f"(c2), "+f"(c3) \
        : "r"(a0), "r"(a1), "r"(a2), "r"(a3), "r"(b0), "r"(b1))

// ---------------------------------------------------------------------------
// SMEM: per stage: A 128x32 fp16, B 128x32 fp16, padded stride 40 (80B rows).
// 4 stages = 80 KB -> 2 CTAs/SM.
// ---------------------------------------------------------------------------
#define SSTR 40
#define A_ELEMS (128 * SSTR)               // 5120
#define OFF_A 0
#define OFF_B A_ELEMS
#define STAGE_ELEMS (2 * A_ELEMS)          // 10240
#define NSTAGE 4
#define SMEM_BYTES (NSTAGE * STAGE_ELEMS * 2)   // 81920

// ---------------------------------------------------------------------------
// fp16 GEMM on HMMA (fp32 accum):  C[M,N] = act( A @ B^T + bias )
// A logically = concat(A0[:, :Ks], A1[:, Ks:]) row-major, fp16.
// CTA tile 128x128, warp tile 64x32, K-chunk 32, 4-stage cp.async pipeline
// with a SINGLE __syncthreads() per chunk.
// ACT: 0 none, 1 exact gelu, 2 sigmoid.
// OUTMODE: 0 = fp32 only, 1 = fp32 + fp16, 2 = fp16 only.
// ---------------------------------------------------------------------------
template<int ACT, int OUTMODE>
__global__ void __launch_bounds__(256, 2)
gemm_mma(const __half* __restrict__ a0h, const __half* __restrict__ a1h, int Ks,
         const __half* __restrict__ bhp,
         const float* __restrict__ bias, float* __restrict__ C,
         __half* __restrict__ ohi,
         int M, int N, int K)
{
    extern __shared__ __align__(128) char smem[];
    const uint32_t sbase = smem_u32(smem);
    const int tid  = threadIdx.x;
    const int warp = tid >> 5;
    const int lane = tid & 31;
    const int bm = blockIdx.y * 128;
    const int bn = blockIdx.x * 128;
    const int wm = (warp >> 2) * 64;       // 0 or 64
    const int wn = (warp & 3) * 32;        // 0..96

    float acc[4][4][4];
#pragma unroll
    for (int i = 0; i < 4; i++)
#pragma unroll
        for (int j = 0; j < 4; j++)
#pragma unroll
            for (int r = 0; r < 4; r++) acc[i][j][r] = 0.0f;

    const int nk = K / 32;

    // ---- stage loader: 2 chunks/thread each for A and B ----
    auto load_stage = [&](int stage, int k0) {
        const __half* ah;
        int lda, kk;
        if (k0 < Ks) { ah = a0h; lda = Ks;     kk = k0; }
        else         { ah = a1h; lda = K - Ks; kk = k0 - Ks; }
        const uint32_t stb = sbase + (uint32_t)stage * STAGE_ELEMS * 2;
#pragma unroll
        for (int r = 0; r < 2; r++) {
            const int c   = tid + r * 256;        // 0..511
            const int row = c >> 2;
            const int seg = c & 3;
            const uint32_t so = stb + (uint32_t)(row * SSTR + seg * 8) * 2;
            CP_ASYNC16(so + OFF_A * 2, ah  + (size_t)(bm + row) * lda + kk + seg * 8);
            CP_ASYNC16(so + OFF_B * 2, bhp + (size_t)(bn + row) * K   + k0 + seg * 8);
        }
        CP_COMMIT();
    };

    // ldmatrix lane geometry
    const int lrow = (lane & 7) + ((lane >> 3) & 1) * 8;   // 0..15
    const int lcol = (lane >> 4) * 8;                      // 0 or 8

    // prologue: fill 3 stages
    load_stage(0, 0);
    load_stage(1, 32);
    load_stage(2, 64);

    for (int kc = 0; kc < nk; kc++) {
        const int rem = nk - 1 - kc;
        if (rem >= 2)      asm volatile("cp.async.wait_group 2;\n" ::: "memory");
        else if (rem == 1) asm volatile("cp.async.wait_group 1;\n" ::: "memory");
        else               asm volatile("cp.async.wait_group 0;\n" ::: "memory");
        __syncthreads();

        if (kc + 3 < nk) load_stage((kc + 3) & 3, (kc + 3) * 32);

        const uint32_t stb = sbase + (uint32_t)(kc & 3) * STAGE_ELEMS * 2;
#pragma unroll
        for (int ks = 0; ks < 2; ks++) {
            const int kb = ks * 16 + lcol;
            uint32_t ah[4][4];
#pragma unroll
            for (int i = 0; i < 4; i++) {
                const uint32_t ad = stb + (uint32_t)((wm + i * 16 + lrow) * SSTR + kb) * 2;
                LDSM_X4(ah[i][0], ah[i][1], ah[i][2], ah[i][3], ad + OFF_A * 2);
            }
#pragma unroll
            for (int p = 0; p < 2; p++) {
                const uint32_t bd = stb + (uint32_t)((wn + p * 16 + lrow) * SSTR + kb) * 2;
                uint32_t b0, b1, b2, b3;
                LDSM_X4(b0, b1, b2, b3, bd + OFF_B * 2);
                const int j0 = 2 * p, j1 = 2 * p + 1;
#pragma unroll
                for (int i = 0; i < 4; i++) {
                    float* c0 = acc[i][j0];
                    float* c1 = acc[i][j1];
                    MMA_F16(c0[0], c0[1], c0[2], c0[3],
                            ah[i][0], ah[i][1], ah[i][2], ah[i][3], b0, b2);
                    MMA_F16(c1[0], c1[1], c1[2], c1[3],
                            ah[i][0], ah[i][1], ah[i][2], ah[i][3], b1, b3);
                }
            }
        }
    }

    // ---- epilogue: bias + activation; fp32 and/or fp16 stores ----
    const int tr = lane >> 2;
    const int tc = (lane & 3) * 2;
#pragma unroll
    for (int i = 0; i < 4; i++) {
        const int r0 = bm + wm + i * 16 + tr;
        const int r1 = r0 + 8;
#pragma unroll
        for (int j = 0; j < 4; j++) {
            const int col = bn + wn + j * 8 + tc;
            const float b0 = bias[col], b1 = bias[col + 1];
            float v[4] = {acc[i][j][0] + b0, acc[i][j][1] + b1,
                          acc[i][j][2] + b0, acc[i][j][3] + b1};
#pragma unroll
            for (int r = 0; r < 4; r++) {
                if (ACT == 1)      v[r] = 0.5f * v[r] * (1.0f + erff(v[r] * 0.70710678118654752f));
                else if (ACT == 2) v[r] = 1.0f / (1.0f + expf(-v[r]));
            }
            if (OUTMODE != 2) {
                *(float2*)(C + (size_t)r0 * N + col) = make_float2(v[0], v[1]);
                *(float2*)(C + (size_t)r1 * N + col) = make_float2(v[2], v[3]);
            }
            if (OUTMODE != 0) {
                *(__half2*)(ohi + (size_t)r0 * N + col) = __floats2half2_rn(v[0], v[1]);
                *(__half2*)(ohi + (size_t)r1 * N + col) = __floats2half2_rn(v[2], v[3]);
            }
        }
    }
}

// ---------------------------------------------------------------------------
// fused fp32 -> fp16 conversion over up to 4 buffers (sizes in float4 units)
// ---------------------------------------------------------------------------
__global__ void __launch_bounds__(256)
cvt4_kernel(const float* __restrict__ i0, __half* __restrict__ o0, int n0,
            const float* __restrict__ i1, __half* __restrict__ o1, int n1,
            const float* __restrict__ i2, __half* __restrict__ o2, int n2,
            const float* __restrict__ i3, __half* __restrict__ o3, int n3)
{
    int t = blockIdx.x * 256 + threadIdx.x;
    const float* in; __half* out;
    if      (t < n0)               { in = i0; out = o0; }
    else if (t < n0 + n1)          { t -= n0;            in = i1; out = o1; }
    else if (t < n0 + n1 + n2)     { t -= n0 + n1;       in = i2; out = o2; }
    else if (t < n0 + n1 + n2 + n3){ t -= n0 + n1 + n2;  in = i3; out = o3; }
    else return;
    float4 v = ((const float4*)in)[t];
    ((__half2*)out)[2 * t]     = __floats2half2_rn(v.x, v.y);
    ((__half2*)out)[2 * t + 1] = __floats2half2_rn(v.z, v.w);
}

// ---------------------------------------------------------------------------
// 4-key attention; reads x_proj/q fp16, h fp32; writes attn fp16.
// ---------------------------------------------------------------------------
__global__ void __launch_bounds__(256)
attn_kernel(const float* __restrict__ h_prev, const __half* __restrict__ xproj,
            const __half* __restrict__ q, __half* __restrict__ ah)
{
    const int gw   = (blockIdx.x * 256 + threadIdx.x) >> 5;
    const int lane = threadIdx.x & 31;
    if (gw >= B_ * NH_) return;
    const size_t base = (size_t)(gw / NH_) * H_ + (size_t)(gw % NH_) * HD_ + lane * 16;

    const float4* hp = (const float4*)(h_prev + base);
    const uint4*  xp = (const uint4*)(xproj + base);
    const uint4*  qp = (const uint4*)(q + base);

    float hf[16], xf[16], qf[16];
#pragma unroll
    for (int k = 0; k < 4; k++) {
        float4 h4 = hp[k];
        hf[4*k] = h4.x; hf[4*k+1] = h4.y; hf[4*k+2] = h4.z; hf[4*k+3] = h4.w;
    }
#pragma unroll
    for (int k = 0; k < 2; k++) {
        uint4 u = xp[k];
        const __half2* p = (const __half2*)&u;
#pragma unroll
        for (int m = 0; m < 4; m++) {
            float2 t = __half22float2(p[m]);
            xf[8*k + 2*m] = t.x; xf[8*k + 2*m + 1] = t.y;
        }
        uint4 uq = qp[k];
        const __half2* pq = (const __half2*)&uq;
#pragma unroll
        for (int m = 0; m < 4; m++) {
            float2 t = __half22float2(pq[m]);
            qf[8*k + 2*m] = t.x; qf[8*k + 2*m + 1] = t.y;
        }
    }

    float s0 = 0.f, s1 = 0.f, s3 = 0.f;
#pragma unroll
    for (int k = 0; k < 16; k++) {
        s0 += qf[k] * hf[k];
        s1 += qf[k] * xf[k];
        s3 += qf[k] * hf[k] * xf[k];
    }
#pragma unroll
    for (int off = 16; off > 0; off >>= 1) {
        s0 += __shfl_xor_sync(0xffffffffu, s0, off);
        s1 += __shfl_xor_sync(0xffffffffu, s1, off);
        s3 += __shfl_xor_sync(0xffffffffu, s3, off);
    }
    const float inv = rsqrtf((float)HD_);
    float sc0 = s0 * inv, sc1 = s1 * inv, sc2 = (s0 + s1) * inv, sc3 = s3 * inv;
    float m  = fmaxf(fmaxf(sc0, sc1), fmaxf(sc2, sc3));
    float e0 = expf(sc0 - m), e1 = expf(sc1 - m), e2 = expf(sc2 - m), e3 = expf(sc3 - m);
    float rs = 1.0f / (e0 + e1 + e2 + e3);
    float w0 = e0 * rs, w1 = e1 * rs, w2 = e2 * rs, w3 = e3 * rs;
    float ch = w0 + w2, cx = w1 + w2;

    __half2 oh[8];
#pragma unroll
    for (int k = 0; k < 8; k++) {
        float o0 = ch * hf[2*k]   + cx * xf[2*k]   + w3 * hf[2*k]   * xf[2*k];
        float o1 = ch * hf[2*k+1] + cx * xf[2*k+1] + w3 * hf[2*k+1] * xf[2*k+1];
        oh[k] = __floats2half2_rn(o0, o1);
    }
    uint4* op = (uint4*)(ah + base);
    op[0] = *(uint4*)&oh[0];
    op[1] = *(uint4*)&oh[4];
}

// ---------------------------------------------------------------------------
// LayerNorm + gated mix (gate fp16)
// ---------------------------------------------------------------------------
__global__ void __launch_bounds__(256)
ln_gate_kernel(const float* __restrict__ attn_g, const float* __restrict__ h_prev,
               const __half* __restrict__ gate, const float* __restrict__ gamma,
               const float* __restrict__ beta, float* __restrict__ out)
{
    const int b   = blockIdx.x;
    const int tid = threadIdx.x;
    const size_t rb = (size_t)b * H_;

    float4 y[2], h4[2];
    float sum = 0.f, sq = 0.f;
#pragma unroll
    for (int c = 0; c < 2; c++) {
        int d = c * 1024 + tid * 4;
        float4 a  = *(const float4*)(attn_g + rb + d);
        float4 hh = *(const float4*)(h_prev + rb + d);
        float4 yy = make_float4(a.x + hh.x, a.y + hh.y, a.z + hh.z, a.w + hh.w);
        y[c] = yy; h4[c] = hh;
        sum += yy.x + yy.y + yy.z + yy.w;
        sq  += yy.x * yy.x + yy.y * yy.y + yy.z * yy.z + yy.w * yy.w;
    }
#pragma unroll
    for (int off = 16; off > 0; off >>= 1) {
        sum += __shfl_xor_sync(0xffffffffu, sum, off);
        sq  += __shfl_xor_sync(0xffffffffu, sq,  off);
    }
    __shared__ float s_sum[8], s_sq[8];
    __shared__ float s_mu, s_rstd;
    if ((tid & 31) == 0) { s_sum[tid >> 5] = sum; s_sq[tid >> 5] = sq; }
    __syncthreads();
    if (tid == 0) {
        float S = 0.f, Q = 0.f;
#pragma unroll
        for (int i = 0; i < 8; i++) { S += s_sum[i]; Q += s_sq[i]; }
        float mu  = S / (float)H_;
        float var = Q / (float)H_ - mu * mu;
        s_mu = mu;
        s_rstd = rsqrtf(var + EPS_);
    }
    __syncthreads();
    const float mu = s_mu, rstd = s_rstd;

#pragma unroll
    for (int c = 0; c < 2; c++) {
        int d = c * 1024 + tid * 4;
        const __half2* gp = (const __half2*)(gate + rb + d);
        float2 g01 = __half22float2(gp[0]);
        float2 g23 = __half22float2(gp[1]);
        float4 gm = *(const float4*)(gamma + d);
        float4 bt = *(const float4*)(beta  + d);
        float4 yy = y[c], hh = h4[c], o;
        float c0 = (yy.x - mu) * rstd * gm.x + bt.x;
        float c1 = (yy.y - mu) * rstd * gm.y + bt.y;
        float c2 = (yy.z - mu) * rstd * gm.z + bt.z;
        float c3 = (yy.w - mu) * rstd * gm.w + bt.w;
        o.x = g01.x * c0 + (1.0f - g01.x) * hh.x;
        o.y = g01.y * c1 + (1.0f - g01.y) * hh.y;
        o.z = g23.x * c2 + (1.0f - g23.x) * hh.z;
        o.w = g23.y * c3 + (1.0f - g23.y) * hh.w;
        *(float4*)(out + rb + d) = o;
    }
}

// ---------------------------------------------------------------------------
extern "C" void kernel_launch(void* const* d_in, const int* in_sizes, int n_in,
                              void* d_out, int out_size)
{
    const float* h_prev = (const float*)d_in[0];
    const float* x      = (const float*)d_in[1];
    const float* W_proj = (const float*)d_in[2];
    const float* b_proj = (const float*)d_in[3];
    const float* W_q    = (const float*)d_in[4];
    const float* b_q    = (const float*)d_in[5];
    const float* W_o    = (const float*)d_in[6];
    const float* b_o    = (const float*)d_in[7];
    const float* W_g    = (const float*)d_in[8];
    const float* b_g    = (const float*)d_in[9];
    const float* gamma  = (const float*)d_in[10];
    const float* beta   = (const float*)d_in[11];
    float* out = (float*)d_out;

    float *buf2;
    __half *xsh, *hsh, *xph, *qh, *ath, *agh;
    __half *wph, *wqh, *woh, *wgh;
    cudaGetSymbolAddress((void**)&buf2, g_buf2);
    cudaGetSymbolAddress((void**)&xsh, g_xs_h);
    cudaGetSymbolAddress((void**)&hsh, g_hs_h);
    cudaGetSymbolAddress((void**)&xph, g_xp_h);
    cudaGetSymbolAddress((void**)&qh,  g_q_h);
    cudaGetSymbolAddress((void**)&ath, g_at_h);
    cudaGetSymbolAddress((void**)&agh, g_ag_h);
    cudaGetSymbolAddress((void**)&wph, g_wp_h);
    cudaGetSymbolAddress((void**)&wqh, g_wq_h);
    cudaGetSymbolAddress((void**)&woh, g_wo_h);
    cudaGetSymbolAddress((void**)&wgh, g_wg_h);

    cudaFuncSetAttribute(gemm_mma<0, 2>, cudaFuncAttributeMaxDynamicSharedMemorySize, SMEM_BYTES);
    cudaFuncSetAttribute(gemm_mma<1, 1>, cudaFuncAttributeMaxDynamicSharedMemorySize, SMEM_BYTES);
    cudaFuncSetAttribute(gemm_mma<2, 2>, cudaFuncAttributeMaxDynamicSharedMemorySize, SMEM_BYTES);

    // --- launch #0: weight conversions (fused) ---
    {
        int n0 = H_ * IN_ / 4;       // W_proj
        int n1 = H_ * H_ / 4;        // W_q
        int n2 = H_ * H_ / 4;        // W_o
        int n3 = H_ * 2 * H_ / 4;    // W_g
        int nt = n0 + n1 + n2 + n3;
        cvt4_kernel<<<(nt + 255) / 256, 256>>>(
            W_proj, wph, n0, W_q, wqh, n1, W_o, woh, n2, W_g, wgh, n3);
    }
    // --- launch #1: activation conversions (fused) ---
    {
        int n0 = B_ * IN_ / 4;       // x
        int n1 = B_ * H_ / 4;        // h_prev
        int nt = n0 + n1;
        cvt4_kernel<<<(nt + 255) / 256, 256>>>(
            x, xsh, n0, h_prev, hsh, n1, x, xsh, 0, x, xsh, 0);
    }

    dim3 grid(H_ / 128, B_ / 128);   // (16, 64) = 1024 CTAs

    // #2) x_proj (fp16 only)
    gemm_mma<0, 2><<<grid, 256, SMEM_BYTES>>>(
        xsh, xsh, IN_, wph, b_proj, nullptr, xph, B_, H_, IN_);
    // #3) q (fp16 only)
    gemm_mma<0, 2><<<grid, 256, SMEM_BYTES>>>(
        hsh, hsh, H_, wqh, b_q, nullptr, qh, B_, H_, H_);
    // #4) attention -> attn fp16
    attn_kernel<<<(B_ * NH_) / 8, 256>>>(h_prev, xph, qh, ath);
    // #5) attn_gelu (fp32 + fp16)   <- profiled by ncu -s 5
    gemm_mma<1, 1><<<grid, 256, SMEM_BYTES>>>(
        ath, ath, H_, woh, b_o, buf2, agh, B_, H_, H_);
    // #6) gate (fp16 only, reuses q buffer)
    gemm_mma<2, 2><<<grid, 256, SMEM_BYTES>>>(
        hsh, agh, H_, wgh, b_g, nullptr, qh, B_, H_, 2 * H_);
    // #7) layernorm + gated mix
    ln_gate_kernel<<<B_, 256>>>(buf2, h_prev, qh, gamma, beta, out);
}

// round 10
// speedup vs baseline: 3.1464x; 1.1270x over previous
#include <cuda_runtime.h>
#include <cuda_fp16.h>
#include <math.h>
#include <stdint.h>

#define B_  8192
#define IN_ 1024
#define H_  2048
#define NH_ 4
#define HD_ 512
#define EPS_ 1e-5f

// ---------------------------------------------------------------------------
// Device scratch (allocation-free rule)
// ---------------------------------------------------------------------------
__device__ __align__(128) float g_buf2[(size_t)B_ * H_];   // attn_gelu (fp32)

// fp16 activations / intermediates
__device__ __align__(128) __half g_xs_h[(size_t)B_ * IN_];   // x fp16
__device__ __align__(128) __half g_hs_h[(size_t)B_ * H_];    // h_prev fp16
__device__ __align__(128) __half g_xp_h[(size_t)B_ * H_];    // x_proj fp16
__device__ __align__(128) __half g_q_h [(size_t)B_ * H_];    // q fp16 -> gate fp16
__device__ __align__(128) __half g_at_h[(size_t)B_ * H_];    // attn fp16
__device__ __align__(128) __half g_ag_h[(size_t)B_ * H_];    // attn_gelu fp16

// fp16 weights
__device__ __align__(128) __half g_wp_h[(size_t)H_ * IN_];
__device__ __align__(128) __half g_wq_h[(size_t)H_ * H_];
__device__ __align__(128) __half g_wo_h[(size_t)H_ * H_];
__device__ __align__(128) __half g_wg_h[(size_t)H_ * 2 * H_];

// ---------------------------------------------------------------------------
// PTX helpers (base-target-safe)
// ---------------------------------------------------------------------------
__device__ __forceinline__ uint32_t smem_u32(const void* p) {
    uint32_t a;
    asm("{ .reg .u64 t; cvta.to.shared.u64 t, %1; cvt.u32.u64 %0, t; }" : "=r"(a) : "l"(p));
    return a;
}

#define CP_ASYNC16(sa, ga) \
    asm volatile("cp.async.cg.shared.global [%0], [%1], 16;\n" :: "r"(sa), "l"(ga))
#define CP_COMMIT()  asm volatile("cp.async.commit_group;\n" ::: "memory")

#define LDSM_X4(r0, r1, r2, r3, addr) \
    asm volatile("ldmatrix.sync.aligned.m8n8.x4.shared.b16 {%0,%1,%2,%3}, [%4];" \
        : "=r"(r0), "=r"(r1), "=r"(r2), "=r"(r3) : "r"(addr))

#define MMA_F16(c0, c1, c2, c3, a0, a1, a2, a3, b0, b1) \
    asm volatile("mma.sync.aligned.m16n8k16.row.col.f32.f16.f16.f32 " \
        "{%0,%1,%2,%3}, {%4,%5,%6,%7}, {%8,%9}, {%0,%1,%2,%3};" \
        : "+f"(c0), "+f"(c1), "+f"(c2), "+f"(c3) \
        : "r"(a0), "r"(a1), "r"(a2), "r"(a3), "r"(b0), "r"(b1))

// ---------------------------------------------------------------------------
// SMEM: per stage: A 128x64 fp16, B 128x64 fp16, row stride 72 elems (144B:
// 16B-aligned row starts, conflict-free ldmatrix). 3 stages = 108 KB -> 2 CTA/SM.
// ---------------------------------------------------------------------------
#define SSTR 72
#define T_ELEMS (128 * SSTR)               // 9216
#define OFF_A 0
#define OFF_B T_ELEMS
#define STAGE_ELEMS (2 * T_ELEMS)          // 18432
#define NSTAGE 3
#define SMEM_BYTES (NSTAGE * STAGE_ELEMS * 2)   // 110592

// ---------------------------------------------------------------------------
// fp16 GEMM on HMMA (fp32 accum):  C[M,N] = act( A @ B^T + bias )
// A logically = concat(A0[:, :Ks], A1[:, Ks:]) row-major, fp16 (Ks mult of 64).
// CTA tile 128x128, warp tile 64x32, K-chunk 64, 3-stage cp.async pipeline,
// single __syncthreads() per 64-K chunk. Stage indices carried as
// increment-and-wrap counters (no %).
// ACT: 0 none, 1 exact gelu, 2 sigmoid.
// OUTMODE: 0 = fp32 only, 1 = fp32 + fp16, 2 = fp16 only.
// ---------------------------------------------------------------------------
template<int ACT, int OUTMODE>
__global__ void __launch_bounds__(256, 2)
gemm_mma(const __half* __restrict__ a0h, const __half* __restrict__ a1h, int Ks,
         const __half* __restrict__ bhp,
         const float* __restrict__ bias, float* __restrict__ C,
         __half* __restrict__ ohi,
         int M, int N, int K)
{
    extern __shared__ __align__(128) char smem[];
    const uint32_t sbase = smem_u32(smem);
    const int tid  = threadIdx.x;
    const int warp = tid >> 5;
    const int lane = tid & 31;
    const int bm = blockIdx.y * 128;
    const int bn = blockIdx.x * 128;
    const int wm = (warp >> 2) * 64;       // 0 or 64
    const int wn = (warp & 3) * 32;        // 0..96

    float acc[4][4][4];
#pragma unroll
    for (int i = 0; i < 4; i++)
#pragma unroll
        for (int j = 0; j < 4; j++)
#pragma unroll
            for (int r = 0; r < 4; r++) acc[i][j][r] = 0.0f;

    const int nk = K / 64;

    // ---- stage loader: 4 chunks/thread each for A and B ----
    auto load_stage = [&](int stage, int k0) {
        const __half* ah;
        int lda, kk;
        if (k0 < Ks) { ah = a0h; lda = Ks;     kk = k0; }
        else         { ah = a1h; lda = K - Ks; kk = k0 - Ks; }
        const uint32_t stb = sbase + (uint32_t)stage * STAGE_ELEMS * 2;
#pragma unroll
        for (int r = 0; r < 4; r++) {
            const int c   = tid + r * 256;        // 0..1023
            const int row = c >> 3;
            const int seg = c & 7;
            const uint32_t so = stb + (uint32_t)(row * SSTR + seg * 8) * 2;
            CP_ASYNC16(so + OFF_A * 2, ah  + (size_t)(bm + row) * lda + kk + seg * 8);
            CP_ASYNC16(so + OFF_B * 2, bhp + (size_t)(bn + row) * K   + k0 + seg * 8);
        }
        CP_COMMIT();
    };

    // ldmatrix lane geometry; hoisted per-warp base offsets (bytes)
    const int lrow = (lane & 7) + ((lane >> 3) & 1) * 8;   // 0..15
    const int lcol = (lane >> 4) * 8;                      // 0 or 8
    uint32_t aoff[4], boff[2];
#pragma unroll
    for (int i = 0; i < 4; i++)
        aoff[i] = (uint32_t)(((wm + i * 16 + lrow) * SSTR + lcol) * 2) + OFF_A * 2;
#pragma unroll
    for (int p = 0; p < 2; p++)
        boff[p] = (uint32_t)(((wn + p * 16 + lrow) * SSTR + lcol) * 2) + OFF_B * 2;

    // prologue: fill 2 stages
    load_stage(0, 0);
    if (nk > 1) load_stage(1, 64);

    int st_comp = 0;   // stage holding chunk kc
    int st_load = 2;   // stage to receive chunk kc+2

    for (int kc = 0; kc < nk; kc++) {
        if (kc + 1 < nk) asm volatile("cp.async.wait_group 1;\n" ::: "memory");
        else             asm volatile("cp.async.wait_group 0;\n" ::: "memory");
        __syncthreads();

        if (kc + 2 < nk) load_stage(st_load, (kc + 2) * 64);

        const uint32_t stb = sbase + (uint32_t)st_comp * STAGE_ELEMS * 2;
#pragma unroll
        for (int ks = 0; ks < 4; ks++) {
            const uint32_t kadd = stb + (uint32_t)(ks * 16 * 2);
            uint32_t ah[4][4];
#pragma unroll
            for (int i = 0; i < 4; i++)
                LDSM_X4(ah[i][0], ah[i][1], ah[i][2], ah[i][3], kadd + aoff[i]);
#pragma unroll
            for (int p = 0; p < 2; p++) {
                uint32_t b0, b1, b2, b3;
                LDSM_X4(b0, b1, b2, b3, kadd + boff[p]);
                const int j0 = 2 * p, j1 = 2 * p + 1;
#pragma unroll
                for (int i = 0; i < 4; i++) {
                    float* c0 = acc[i][j0];
                    float* c1 = acc[i][j1];
                    MMA_F16(c0[0], c0[1], c0[2], c0[3],
                            ah[i][0], ah[i][1], ah[i][2], ah[i][3], b0, b2);
                    MMA_F16(c1[0], c1[1], c1[2], c1[3],
                            ah[i][0], ah[i][1], ah[i][2], ah[i][3], b1, b3);
                }
            }
        }
        st_comp = (st_comp == NSTAGE - 1) ? 0 : st_comp + 1;
        st_load = (st_load == NSTAGE - 1) ? 0 : st_load + 1;
    }

    // ---- epilogue: bias + activation; fp32 and/or fp16 stores ----
    const int tr = lane >> 2;
    const int tc = (lane & 3) * 2;
#pragma unroll
    for (int i = 0; i < 4; i++) {
        const int r0 = bm + wm + i * 16 + tr;
        const int r1 = r0 + 8;
#pragma unroll
        for (int j = 0; j < 4; j++) {
            const int col = bn + wn + j * 8 + tc;
            const float b0 = bias[col], b1 = bias[col + 1];
            float v[4] = {acc[i][j][0] + b0, acc[i][j][1] + b1,
                          acc[i][j][2] + b0, acc[i][j][3] + b1};
#pragma unroll
            for (int r = 0; r < 4; r++) {
                if (ACT == 1)      v[r] = 0.5f * v[r] * (1.0f + erff(v[r] * 0.70710678118654752f));
                else if (ACT == 2) v[r] = 1.0f / (1.0f + expf(-v[r]));
            }
            if (OUTMODE != 2) {
                *(float2*)(C + (size_t)r0 * N + col) = make_float2(v[0], v[1]);
                *(float2*)(C + (size_t)r1 * N + col) = make_float2(v[2], v[3]);
            }
            if (OUTMODE != 0) {
                *(__half2*)(ohi + (size_t)r0 * N + col) = __floats2half2_rn(v[0], v[1]);
                *(__half2*)(ohi + (size_t)r1 * N + col) = __floats2half2_rn(v[2], v[3]);
            }
        }
    }
}

// ---------------------------------------------------------------------------
// fused fp32 -> fp16 conversion over up to 4 buffers (sizes in float4 units)
// ---------------------------------------------------------------------------
__global__ void __launch_bounds__(256)
cvt4_kernel(const float* __restrict__ i0, __half* __restrict__ o0, int n0,
            const float* __restrict__ i1, __half* __restrict__ o1, int n1,
            const float* __restrict__ i2, __half* __restrict__ o2, int n2,
            const float* __restrict__ i3, __half* __restrict__ o3, int n3)
{
    int t = blockIdx.x * 256 + threadIdx.x;
    const float* in; __half* out;
    if      (t < n0)               { in = i0; out = o0; }
    else if (t < n0 + n1)          { t -= n0;            in = i1; out = o1; }
    else if (t < n0 + n1 + n2)     { t -= n0 + n1;       in = i2; out = o2; }
    else if (t < n0 + n1 + n2 + n3){ t -= n0 + n1 + n2;  in = i3; out = o3; }
    else return;
    float4 v = ((const float4*)in)[t];
    ((__half2*)out)[2 * t]     = __floats2half2_rn(v.x, v.y);
    ((__half2*)out)[2 * t + 1] = __floats2half2_rn(v.z, v.w);
}

// ---------------------------------------------------------------------------
// 4-key attention; reads x_proj/q fp16, h fp32; writes attn fp16.
// ---------------------------------------------------------------------------
__global__ void __launch_bounds__(256)
attn_kernel(const float* __restrict__ h_prev, const __half* __restrict__ xproj,
            const __half* __restrict__ q, __half* __restrict__ ah)
{
    const int gw   = (blockIdx.x * 256 + threadIdx.x) >> 5;
    const int lane = threadIdx.x & 31;
    if (gw >= B_ * NH_) return;
    const size_t base = (size_t)(gw / NH_) * H_ + (size_t)(gw % NH_) * HD_ + lane * 16;

    const float4* hp = (const float4*)(h_prev + base);
    const uint4*  xp = (const uint4*)(xproj + base);
    const uint4*  qp = (const uint4*)(q + base);

    float hf[16], xf[16], qf[16];
#pragma unroll
    for (int k = 0; k < 4; k++) {
        float4 h4 = hp[k];
        hf[4*k] = h4.x; hf[4*k+1] = h4.y; hf[4*k+2] = h4.z; hf[4*k+3] = h4.w;
    }
#pragma unroll
    for (int k = 0; k < 2; k++) {
        uint4 u = xp[k];
        const __half2* p = (const __half2*)&u;
#pragma unroll
        for (int m = 0; m < 4; m++) {
            float2 t = __half22float2(p[m]);
            xf[8*k + 2*m] = t.x; xf[8*k + 2*m + 1] = t.y;
        }
        uint4 uq = qp[k];
        const __half2* pq = (const __half2*)&uq;
#pragma unroll
        for (int m = 0; m < 4; m++) {
            float2 t = __half22float2(pq[m]);
            qf[8*k + 2*m] = t.x; qf[8*k + 2*m + 1] = t.y;
        }
    }

    float s0 = 0.f, s1 = 0.f, s3 = 0.f;
#pragma unroll
    for (int k = 0; k < 16; k++) {
        s0 += qf[k] * hf[k];
        s1 += qf[k] * xf[k];
        s3 += qf[k] * hf[k] * xf[k];
    }
#pragma unroll
    for (int off = 16; off > 0; off >>= 1) {
        s0 += __shfl_xor_sync(0xffffffffu, s0, off);
        s1 += __shfl_xor_sync(0xffffffffu, s1, off);
        s3 += __shfl_xor_sync(0xffffffffu, s3, off);
    }
    const float inv = rsqrtf((float)HD_);
    float sc0 = s0 * inv, sc1 = s1 * inv, sc2 = (s0 + s1) * inv, sc3 = s3 * inv;
    float m  = fmaxf(fmaxf(sc0, sc1), fmaxf(sc2, sc3));
    float e0 = expf(sc0 - m), e1 = expf(sc1 - m), e2 = expf(sc2 - m), e3 = expf(sc3 - m);
    float rs = 1.0f / (e0 + e1 + e2 + e3);
    float w0 = e0 * rs, w1 = e1 * rs, w2 = e2 * rs, w3 = e3 * rs;
    float ch = w0 + w2, cx = w1 + w2;

    __half2 oh[8];
#pragma unroll
    for (int k = 0; k < 8; k++) {
        float o0 = ch * hf[2*k]   + cx * xf[2*k]   + w3 * hf[2*k]   * xf[2*k];
        float o1 = ch * hf[2*k+1] + cx * xf[2*k+1] + w3 * hf[2*k+1] * xf[2*k+1];
        oh[k] = __floats2half2_rn(o0, o1);
    }
    uint4* op = (uint4*)(ah + base);
    op[0] = *(uint4*)&oh[0];
    op[1] = *(uint4*)&oh[4];
}

// ---------------------------------------------------------------------------
// LayerNorm + gated mix (gate fp16)
// ---------------------------------------------------------------------------
__global__ void __launch_bounds__(256)
ln_gate_kernel(const float* __restrict__ attn_g, const float* __restrict__ h_prev,
               const __half* __restrict__ gate, const float* __restrict__ gamma,
               const float* __restrict__ beta, float* __restrict__ out)
{
    const int b   = blockIdx.x;
    const int tid = threadIdx.x;
    const size_t rb = (size_t)b * H_;

    float4 y[2], h4[2];
    float sum = 0.f, sq = 0.f;
#pragma unroll
    for (int c = 0; c < 2; c++) {
        int d = c * 1024 + tid * 4;
        float4 a  = *(const float4*)(attn_g + rb + d);
        float4 hh = *(const float4*)(h_prev + rb + d);
        float4 yy = make_float4(a.x + hh.x, a.y + hh.y, a.z + hh.z, a.w + hh.w);
        y[c] = yy; h4[c] = hh;
        sum += yy.x + yy.y + yy.z + yy.w;
        sq  += yy.x * yy.x + yy.y * yy.y + yy.z * yy.z + yy.w * yy.w;
    }
#pragma unroll
    for (int off = 16; off > 0; off >>= 1) {
        sum += __shfl_xor_sync(0xffffffffu, sum, off);
        sq  += __shfl_xor_sync(0xffffffffu, sq,  off);
    }
    __shared__ float s_sum[8], s_sq[8];
    __shared__ float s_mu, s_rstd;
    if ((tid & 31) == 0) { s_sum[tid >> 5] = sum; s_sq[tid >> 5] = sq; }
    __syncthreads();
    if (tid == 0) {
        float S = 0.f, Q = 0.f;
#pragma unroll
        for (int i = 0; i < 8; i++) { S += s_sum[i]; Q += s_sq[i]; }
        float mu  = S / (float)H_;
        float var = Q / (float)H_ - mu * mu;
        s_mu = mu;
        s_rstd = rsqrtf(var + EPS_);
    }
    __syncthreads();
    const float mu = s_mu, rstd = s_rstd;

#pragma unroll
    for (int c = 0; c < 2; c++) {
        int d = c * 1024 + tid * 4;
        const __half2* gp = (const __half2*)(gate + rb + d);
        float2 g01 = __half22float2(gp[0]);
        float2 g23 = __half22float2(gp[1]);
        float4 gm = *(const float4*)(gamma + d);
        float4 bt = *(const float4*)(beta  + d);
        float4 yy = y[c], hh = h4[c], o;
        float c0 = (yy.x - mu) * rstd * gm.x + bt.x;
        float c1 = (yy.y - mu) * rstd * gm.y + bt.y;
        float c2 = (yy.z - mu) * rstd * gm.z + bt.z;
        float c3 = (yy.w - mu) * rstd * gm.w + bt.w;
        o.x = g01.x * c0 + (1.0f - g01.x) * hh.x;
        o.y = g01.y * c1 + (1.0f - g01.y) * hh.y;
        o.z = g23.x * c2 + (1.0f - g23.x) * hh.z;
        o.w = g23.y * c3 + (1.0f - g23.y) * hh.w;
        *(float4*)(out + rb + d) = o;
    }
}

// ---------------------------------------------------------------------------
extern "C" void kernel_launch(void* const* d_in, const int* in_sizes, int n_in,
                              void* d_out, int out_size)
{
    const float* h_prev = (const float*)d_in[0];
    const float* x      = (const float*)d_in[1];
    const float* W_proj = (const float*)d_in[2];
    const float* b_proj = (const float*)d_in[3];
    const float* W_q    = (const float*)d_in[4];
    const float* b_q    = (const float*)d_in[5];
    const float* W_o    = (const float*)d_in[6];
    const float* b_o    = (const float*)d_in[7];
    const float* W_g    = (const float*)d_in[8];
    const float* b_g    = (const float*)d_in[9];
    const float* gamma  = (const float*)d_in[10];
    const float* beta   = (const float*)d_in[11];
    float* out = (float*)d_out;

    float *buf2;
    __half *xsh, *hsh, *xph, *qh, *ath, *agh;
    __half *wph, *wqh, *woh, *wgh;
    cudaGetSymbolAddress((void**)&buf2, g_buf2);
    cudaGetSymbolAddress((void**)&xsh, g_xs_h);
    cudaGetSymbolAddress((void**)&hsh, g_hs_h);
    cudaGetSymbolAddress((void**)&xph, g_xp_h);
    cudaGetSymbolAddress((void**)&qh,  g_q_h);
    cudaGetSymbolAddress((void**)&ath, g_at_h);
    cudaGetSymbolAddress((void**)&agh, g_ag_h);
    cudaGetSymbolAddress((void**)&wph, g_wp_h);
    cudaGetSymbolAddress((void**)&wqh, g_wq_h);
    cudaGetSymbolAddress((void**)&woh, g_wo_h);
    cudaGetSymbolAddress((void**)&wgh, g_wg_h);

    cudaFuncSetAttribute(gemm_mma<0, 2>, cudaFuncAttributeMaxDynamicSharedMemorySize, SMEM_BYTES);
    cudaFuncSetAttribute(gemm_mma<1, 1>, cudaFuncAttributeMaxDynamicSharedMemorySize, SMEM_BYTES);
    cudaFuncSetAttribute(gemm_mma<2, 2>, cudaFuncAttributeMaxDynamicSharedMemorySize, SMEM_BYTES);

    // --- launch #0: weight conversions (fused) ---
    {
        int n0 = H_ * IN_ / 4;       // W_proj
        int n1 = H_ * H_ / 4;        // W_q
        int n2 = H_ * H_ / 4;        // W_o
        int n3 = H_ * 2 * H_ / 4;    // W_g
        int nt = n0 + n1 + n2 + n3;
        cvt4_kernel<<<(nt + 255) / 256, 256>>>(
            W_proj, wph, n0, W_q, wqh, n1, W_o, woh, n2, W_g, wgh, n3);
    }
    // --- launch #1: activation conversions (fused) ---
    {
        int n0 = B_ * IN_ / 4;       // x
        int n1 = B_ * H_ / 4;        // h_prev
        int nt = n0 + n1;
        cvt4_kernel<<<(nt + 255) / 256, 256>>>(
            x, xsh, n0, h_prev, hsh, n1, x, xsh, 0, x, xsh, 0);
    }

    dim3 grid(H_ / 128, B_ / 128);   // (16, 64) = 1024 CTAs

    // #2) x_proj (fp16 only)
    gemm_mma<0, 2><<<grid, 256, SMEM_BYTES>>>(
        xsh, xsh, IN_, wph, b_proj, nullptr, xph, B_, H_, IN_);
    // #3) q (fp16 only)
    gemm_mma<0, 2><<<grid, 256, SMEM_BYTES>>>(
        hsh, hsh, H_, wqh, b_q, nullptr, qh, B_, H_, H_);
    // #4) attention -> attn fp16
    attn_kernel<<<(B_ * NH_) / 8, 256>>>(h_prev, xph, qh, ath);
    // #5) attn_gelu (fp32 + fp16)   <- profiled by ncu -s 5
    gemm_mma<1, 1><<<grid, 256, SMEM_BYTES>>>(
        ath, ath, H_, woh, b_o, buf2, agh, B_, H_, H_);
    // #6) gate (fp16 only, reuses q buffer)
    gemm_mma<2, 2><<<grid, 256, SMEM_BYTES>>>(
        hsh, agh, H_, wgh, b_g, nullptr, qh, B_, H_, 2 * H_);
    // #7) layernorm + gated mix
    ln_gate_kernel<<<B_, 256>>>(buf2, h_prev, qh, gamma, beta, out);
}